// round 9
// baseline (speedup 1.0000x reference)
#include <cuda_runtime.h>
#include <cuda_bf16.h>
#include <mma.h>
#include <math.h>
#include <stdint.h>

using namespace nvcuda;

#define B_ 32
#define L_ 720
#define N_ 512
#define H_ 16
#define D_ 64
#define TOPK_ 8
#define M_ (B_*L_)   // 23040

// ---------------- scratch (static device memory; no allocations) ----------------
__device__ float g_Q[N_*H_];
__device__ float g_K[N_*H_];
__device__ int   g_idx[N_*TOPK_];
__device__ float g_w[N_*TOPK_];
__device__ float g_logit[B_*L_];
__device__ float g_center_raw[B_*N_];
__device__ float g_center[B_*N_];
__device__ float g_cg[B_*N_];
__device__ __align__(16) float g_ring[(size_t)M_*N_];
__device__ __align__(16) float g_fused[(size_t)M_*N_];
__device__ __align__(16) float g_h[(size_t)M_*N_];

// ---------------- helpers ----------------
__device__ __forceinline__ uint32_t smem_to_u32(const void* p) {
    uint32_t a;
    asm("{ .reg .u64 t; cvta.to.shared.u64 t, %1; cvt.u32.u64 %0, t; }" : "=r"(a) : "l"(p));
    return a;
}
__device__ __forceinline__ void cpa16(uint32_t d, const void* s) {
    asm volatile("cp.async.cg.shared.global [%0], [%1], 16;" :: "r"(d), "l"(s) : "memory");
}
#define CP_COMMIT() asm volatile("cp.async.commit_group;" ::: "memory")
#define CP_WAIT1()  asm volatile("cp.async.wait_group 1;" ::: "memory")
#define CP_WAIT0()  asm volatile("cp.async.wait_group 0;" ::: "memory")

// ---------------- 1. Q/K projection ----------------
__global__ void qk_kernel(const float* __restrict__ ve,
                          const float* __restrict__ Wq, const float* __restrict__ bq,
                          const float* __restrict__ Wk, const float* __restrict__ bk) {
    int n = blockIdx.x * blockDim.x + threadIdx.x;
    if (n >= N_) return;
    float v[H_];
#pragma unroll
    for (int j = 0; j < H_; j++) v[j] = ve[n*H_+j];
#pragma unroll
    for (int h = 0; h < H_; h++) {
        float q = bq[h], k = bk[h];
#pragma unroll
        for (int j = 0; j < H_; j++) { q += v[j]*Wq[j*H_+h]; k += v[j]*Wk[j*H_+h]; }
        g_Q[n*H_+h] = q; g_K[n*H_+h] = k;
    }
}

// ---------------- 2. top-8 + softmax weights ----------------
__global__ void topk_kernel() {
    int n = blockIdx.x, tid = threadIdx.x;   // 128 threads
    __shared__ float sim[N_];
    __shared__ float q[H_];
    __shared__ float rv[128];
    __shared__ int   ri[128];
    __shared__ float tv[TOPK_];
    __shared__ int   tix[TOPK_];
    if (tid < H_) q[tid] = g_Q[n*H_+tid];
    __syncthreads();
    for (int m = tid; m < N_; m += 128) {
        float s = 0.f;
#pragma unroll
        for (int j = 0; j < H_; j++) s += q[j]*g_K[m*H_+j];
        sim[m] = (m == n) ? -1e9f : s;
    }
    __syncthreads();
    for (int t = 0; t < TOPK_; t++) {
        float bv = -1e30f; int bi = 0x7fffffff;
        for (int m = tid; m < N_; m += 128) {
            float s = sim[m];
            if (s > bv) { bv = s; bi = m; }
        }
        rv[tid] = bv; ri[tid] = bi;
        __syncthreads();
        for (int off = 64; off > 0; off >>= 1) {
            if (tid < off) {
                float ov = rv[tid+off]; int oi = ri[tid+off];
                if (ov > rv[tid] || (ov == rv[tid] && oi < ri[tid])) { rv[tid] = ov; ri[tid] = oi; }
            }
            __syncthreads();
        }
        if (tid == 0) { tv[t] = rv[0]; tix[t] = ri[0]; sim[ri[0]] = -1e30f; }
        __syncthreads();
    }
    if (tid == 0) {
        float mx = tv[0], e[TOPK_], s = 0.f;
#pragma unroll
        for (int t = 0; t < TOPK_; t++) { e[t] = expf(tv[t]-mx); s += e[t]; }
        float inv = 1.f/s;
#pragma unroll
        for (int t = 0; t < TOPK_; t++) { g_w[n*TOPK_+t] = e[t]*inv; g_idx[n*TOPK_+t] = tix[t]; }
    }
}

// ---------------- 3a. score logits ----------------
__global__ void score_kernel(const float* __restrict__ x,
                             const float* __restrict__ Wscore,
                             const float* __restrict__ bscore) {
    int b = blockIdx.y, l0 = blockIdx.x * 90;
    int w = threadIdx.x >> 5, lane = threadIdx.x & 31;
    for (int l = l0 + w; l < l0 + 90; l += 8) {
        const float4* xr = (const float4*)(x + ((size_t)b*L_+l)*N_);
        const float4* wr = (const float4*)Wscore;
        float s = 0.f;
#pragma unroll
        for (int c = 0; c < 4; c++) {
            float4 v = xr[lane + c*32], ww = wr[lane + c*32];
            s += v.x*ww.x + v.y*ww.y + v.z*ww.z + v.w*ww.w;
        }
#pragma unroll
        for (int o = 16; o > 0; o >>= 1) s += __shfl_xor_sync(0xffffffffu, s, o);
        if (lane == 0) g_logit[b*L_+l] = s + bscore[0];
    }
}

// ---------------- 3b. fused softmax-over-L + weighted sum ----------------
__global__ void csum_kernel(const float* __restrict__ x) {
    int b = blockIdx.y, c = blockIdx.x*128 + threadIdx.x;
    int tid = threadIdx.x;   // 128 threads
    __shared__ float p[L_];
    __shared__ float red[128];
    for (int l = tid; l < L_; l += 128) p[l] = g_logit[b*L_+l];
    __syncthreads();
    float m = -1e30f;
    for (int l = tid; l < L_; l += 128) m = fmaxf(m, p[l]);
    red[tid] = m; __syncthreads();
    for (int o = 64; o > 0; o >>= 1) { if (tid < o) red[tid] = fmaxf(red[tid], red[tid+o]); __syncthreads(); }
    m = red[0]; __syncthreads();
    float s = 0.f;
    for (int l = tid; l < L_; l += 128) { float e = expf(p[l]-m); p[l] = e; s += e; }
    red[tid] = s; __syncthreads();
    for (int o = 64; o > 0; o >>= 1) { if (tid < o) red[tid] += red[tid+o]; __syncthreads(); }
    float inv = 1.f/red[0];
    __syncthreads();
    for (int l = tid; l < L_; l += 128) p[l] *= inv;
    __syncthreads();
    float acc = 0.f;
    const float* xb = x + (size_t)b*L_*N_ + c;
    for (int l = 0; l < L_; l++) acc += p[l]*xb[(size_t)l*N_];
    g_center_raw[b*N_+c] = acc;
}

// ---------------- 4a. center MLP ----------------
__global__ void mlp_kernel(const float* __restrict__ Wc1, const float* __restrict__ bc1,
                           const float* __restrict__ Wc2, const float* __restrict__ bc2,
                           const float* __restrict__ Wcn, const float* __restrict__ bcn) {
    int b = blockIdx.x, tid = threadIdx.x;   // 256 threads
    __shared__ float cr[N_];
    __shared__ float c1[D_];
    __shared__ float c2[D_];
    for (int n = tid; n < N_; n += 256) cr[n] = g_center_raw[b*N_+n];
    __syncthreads();
    {
        int d = tid >> 2, part = tid & 3;
        float s = 0.f;
        for (int n = part*128; n < part*128+128; n++) s += cr[n]*Wc1[n*D_+d];
        s += __shfl_xor_sync(0xffffffffu, s, 1);
        s += __shfl_xor_sync(0xffffffffu, s, 2);
        if (part == 0) {
            s += bc1[d];
            c1[d] = 0.5f*s*(1.f + erff(s*0.7071067811865475f));
        }
    }
    __syncthreads();
    if (tid < D_) {
        float s = bc2[tid];
#pragma unroll
        for (int e = 0; e < D_; e++) s += c1[e]*Wc2[e*D_+tid];
        c2[tid] = 0.5f*s*(1.f + erff(s*0.7071067811865475f));
    }
    __syncthreads();
    for (int n = tid; n < N_; n += 256) {
        float s = bcn[n];
#pragma unroll
        for (int d = 0; d < D_; d++) s += c2[d]*Wcn[d*N_+n];
        g_center[b*N_+n] = s;
    }
}

// ---------------- 4b. cg = center @ Wg[N:2N] ----------------
__global__ void cg_kernel(const float* __restrict__ Wg) {
    int b = blockIdx.x, n2 = blockIdx.y*128 + threadIdx.x;
    __shared__ float ctr[N_];
    for (int n = threadIdx.x; n < N_; n += 128) ctr[n] = g_center[b*N_+n];
    __syncthreads();
    float s = 0.f;
    for (int n = 0; n < N_; n++) s += ctr[n]*Wg[(size_t)(N_+n)*N_ + n2];
    g_cg[b*N_+n2] = s;
}

// ---------------- 5. ring gather ----------------
#define TL 8
__global__ void ring_kernel(const float* __restrict__ x) {
    int b = blockIdx.y, l0 = blockIdx.x * TL, tid = threadIdx.x;   // 256 threads
    __shared__ float xt[TL][N_];
    const float* xb = x + (size_t)b*L_*N_ + (size_t)l0*N_;
    for (int i = tid; i < TL*N_/4; i += 256)
        ((float4*)xt)[i] = ((const float4*)xb)[i];
    __syncthreads();
    float* outb = g_ring + (size_t)b*L_*N_ + (size_t)l0*N_;
    for (int o = tid; o < TL*N_; o += 256) {
        int l = o >> 9, n = o & 511;
        float acc = 0.f;
#pragma unroll
        for (int k = 0; k < TOPK_; k++) {
            int id  = __ldg(&g_idx[n*TOPK_+k]);
            float w = __ldg(&g_w[n*TOPK_+k]);
            acc += xt[l][id] * w;
        }
        outb[o] = acc;
    }
}

// ---------------- 6. WMMA tf32 GEMM, BK=32, cp.async double-buffered -----------------
// C = A @ W   (A: M x 512 fp32 row-major; W: 512 x 512 fp32 row-major used directly)
// mode 0: A=g_ring,  W=Wg(top rows);  epi: sigmoid gate mix -> g_fused (fp32)
// mode 1: A=g_fused, W=Wf;            epi: raw product -> g_h (bias+residual in ln)
#define BM_ 128
#define BN_ 128
#define BK_ 32
#define A_LDF 36     // fp32 elems per A smem row (32 + 4 pad; 144 B, 16B-aligned)
#define W_LDF 132    // fp32 elems per W smem row (128 + 4 pad; 528 B, 16B-aligned)
#define SA_OFF 0
#define SW_OFF 18432                 // 128*36*4
#define BUF_B_ 35328                 // + 32*132*4 = 16896
#define GEMM_SMEM_ (2*BUF_B_)        // 70656
#define STG_LD 68    // fp32 staging row stride (mode-0 epilogue; 8*16*68*4 = 34816 < smem)

__global__ __launch_bounds__(256) void gemm_wmma(int mode,
                                                 const float* __restrict__ Wmat,
                                                 const float* __restrict__ e0) {
    extern __shared__ __align__(128) char smem[];
    const int tid = threadIdx.x, wid = tid >> 5, lane = tid & 31;
    const int wm = wid >> 1, wn = wid & 1;   // warp grid 4(m) x 2(n): warp tile 32 x 64
    const int row0 = blockIdx.x * BM_, col0 = blockIdx.y * BN_;
    const uint32_t sbase = smem_to_u32(smem);

    const float* A = (mode == 0) ? g_ring : g_fused;

    wmma::fragment<wmma::accumulator, 16, 16, 8, float> facc[2][4];
#pragma unroll
    for (int mi = 0; mi < 2; mi++)
#pragma unroll
        for (int p = 0; p < 4; p++) wmma::fill_fragment(facc[mi][p], 0.f);

    // cp.async staging: A 128x32 fp32 (1024 chunks) + W 32x128 fp32 (1024 chunks), 8/thread
    auto issue = [&](int kb, int buf) {
        const int k0 = kb * BK_;
        const uint32_t bb = sbase + (uint32_t)buf * BUF_B_;
#pragma unroll
        for (int i = 0; i < 4; i++) {       // A chunks
            int c = i*256 + tid;
            int row = c >> 3, col4 = (c & 7) * 4;
            cpa16(bb + SA_OFF + (uint32_t)(row*A_LDF + col4)*4,
                  A + (size_t)(row0+row)*N_ + k0 + col4);
        }
#pragma unroll
        for (int i = 0; i < 4; i++) {       // W chunks
            int c = i*256 + tid;
            int row = c >> 5, col4 = (c & 31) * 4;
            cpa16(bb + SW_OFF + (uint32_t)(row*W_LDF + col4)*4,
                  Wmat + (size_t)(k0+row)*N_ + col0 + col4);
        }
        CP_COMMIT();
    };

    const int NKB = N_ / BK_;   // 16
    issue(0, 0);
    for (int kb = 0; kb < NKB; kb++) {
        const int buf = kb & 1;
        if (kb + 1 < NKB) { issue(kb + 1, buf ^ 1); CP_WAIT1(); }
        else              { CP_WAIT0(); }
        __syncthreads();

        const char* bb = smem + buf * BUF_B_;
        const float* sA = (const float*)(bb + SA_OFF);
        const float* sW = (const float*)(bb + SW_OFF);

#pragma unroll
        for (int ks = 0; ks < 4; ks++) {    // 4 x K=8
            wmma::fragment<wmma::matrix_a, 16, 16, 8, wmma::precision::tf32, wmma::row_major> fa[2];
#pragma unroll
            for (int mi = 0; mi < 2; mi++) {
                wmma::load_matrix_sync(fa[mi], sA + (wm*32 + mi*16)*A_LDF + ks*8, A_LDF);
#pragma unroll
                for (int t = 0; t < fa[mi].num_elements; t++)
                    fa[mi].x[t] = wmma::__float_to_tf32(fa[mi].x[t]);
            }
#pragma unroll
            for (int p = 0; p < 4; p++) {
                wmma::fragment<wmma::matrix_b, 16, 16, 8, wmma::precision::tf32, wmma::row_major> fb;
                wmma::load_matrix_sync(fb, sW + (ks*8)*W_LDF + wn*64 + p*16, W_LDF);
#pragma unroll
                for (int t = 0; t < fb.num_elements; t++)
                    fb.x[t] = wmma::__float_to_tf32(fb.x[t]);
#pragma unroll
                for (int mi = 0; mi < 2; mi++)
                    wmma::mma_sync(facc[mi][p], fa[mi], fb, facc[mi][p]);
            }
        }
        __syncthreads();   // MMA(kb) done before issue(kb+2) overwrites this buf
    }

    if (mode == 1) {
#pragma unroll
        for (int mi = 0; mi < 2; mi++)
#pragma unroll
            for (int p = 0; p < 4; p++) {
                float* dst = g_h + (size_t)(row0 + wm*32 + mi*16)*N_ + col0 + wn*64 + p*16;
                wmma::store_matrix_sync(dst, facc[mi][p], N_, wmma::mem_row_major);
            }
        return;
    }

    // ---- mode 0 epilogue: two passes of 16 rows via per-warp smem staging ----
    float* wst = (float*)smem + wid * (16 * STG_LD);
#pragma unroll
    for (int mi = 0; mi < 2; mi++) {
#pragma unroll
        for (int p = 0; p < 4; p++)
            wmma::store_matrix_sync(wst + p*16, facc[mi][p], STG_LD, wmma::mem_row_major);
        __syncwarp();
        int r16 = lane >> 1;
        int coff = (lane & 1) * 32;
        int r = row0 + wm*32 + mi*16 + r16;
        int bb = r / L_;
        size_t rb = (size_t)r * N_;
        const float* myrow = wst + r16*STG_LD + coff;
#pragma unroll
        for (int q = 0; q < 8; q++) {
            float4 v = *(const float4*)(myrow + q*4);
            int c = col0 + wn*64 + coff + q*4;
            float4 o;
#pragma unroll
            for (int t = 0; t < 4; t++) {
                int cc = c + t;
                float vv = (&v.x)[t];
                float pre = vv + g_cg[bb*N_+cc] + e0[cc];
                float g = 1.f/(1.f + expf(-pre));
                float rv = g_ring[rb+cc];
                (&o.x)[t] = g*rv + (1.f-g)*g_center[bb*N_+cc];
            }
            *(float4*)(g_fused + rb + c) = o;
        }
        __syncwarp();
    }
}

// ---------------- 7. LayerNorm over N (+ folded Wf bias and residual) ----------------
__global__ void ln_kernel(const float* __restrict__ gamma, const float* __restrict__ beta,
                          const float* __restrict__ bf, const float* __restrict__ x,
                          float* __restrict__ out) {
    int r = blockIdx.x, tid = threadIdx.x;   // 256 threads
    size_t base = (size_t)r*N_;
    float a  = g_h[base+tid]     + bf[tid]     + x[base+tid];
    float b2 = g_h[base+tid+256] + bf[tid+256] + x[base+tid+256];
    __shared__ float rs[256], rq[256];
    rs[tid] = a + b2;
    rq[tid] = a*a + b2*b2;
    __syncthreads();
    for (int o = 128; o > 0; o >>= 1) {
        if (tid < o) { rs[tid] += rs[tid+o]; rq[tid] += rq[tid+o]; }
        __syncthreads();
    }
    float mu  = rs[0] * (1.f/N_);
    float var = rq[0] * (1.f/N_) - mu*mu;
    float inv = rsqrtf(var + 1e-5f);
    out[base+tid]     = (a  - mu)*inv*gamma[tid]     + beta[tid];
    out[base+tid+256] = (b2 - mu)*inv*gamma[tid+256] + beta[tid+256];
}

// ---------------- launch ----------------
extern "C" void kernel_launch(void* const* d_in, const int* in_sizes, int n_in,
                              void* d_out, int out_size) {
    const float* x      = (const float*)d_in[0];
    const float* ve     = (const float*)d_in[1];
    const float* Wq     = (const float*)d_in[2];
    const float* bq     = (const float*)d_in[3];
    const float* Wk     = (const float*)d_in[4];
    const float* bk     = (const float*)d_in[5];
    const float* Wscore = (const float*)d_in[6];
    const float* bscore = (const float*)d_in[7];
    const float* Wc1    = (const float*)d_in[8];
    const float* bc1    = (const float*)d_in[9];
    const float* Wc2    = (const float*)d_in[10];
    const float* bc2    = (const float*)d_in[11];
    const float* Wcn    = (const float*)d_in[12];
    const float* bcn    = (const float*)d_in[13];
    const float* Wg     = (const float*)d_in[14];
    const float* bg     = (const float*)d_in[15];
    const float* Wf     = (const float*)d_in[16];
    const float* bf     = (const float*)d_in[17];
    const float* gamma  = (const float*)d_in[18];
    const float* beta   = (const float*)d_in[19];
    float* out = (float*)d_out;

    cudaFuncSetAttribute(gemm_wmma, cudaFuncAttributeMaxDynamicSharedMemorySize, GEMM_SMEM_);

    qk_kernel<<<2, 256>>>(ve, Wq, bq, Wk, bk);
    topk_kernel<<<512, 128>>>();
    score_kernel<<<dim3(8, B_), 256>>>(x, Wscore, bscore);
    csum_kernel<<<dim3(4, B_), 128>>>(x);      // fused softmax + weighted sum
    mlp_kernel<<<B_, 256>>>(Wc1, bc1, Wc2, bc2, Wcn, bcn);
    cg_kernel<<<dim3(B_, 4), 128>>>(Wg);
    ring_kernel<<<dim3(L_/TL, B_), 256>>>(x);

    gemm_wmma<<<dim3(M_/BM_, N_/BN_), 256, GEMM_SMEM_>>>(0, Wg, bg);
    gemm_wmma<<<dim3(M_/BM_, N_/BN_), 256, GEMM_SMEM_>>>(1, Wf, nullptr);

    ln_kernel<<<M_, 256>>>(gamma, beta, bf, x, out);
}

// round 10
// speedup vs baseline: 1.0282x; 1.0282x over previous
#include <cuda_runtime.h>
#include <cuda_bf16.h>
#include <mma.h>
#include <math.h>
#include <stdint.h>

using namespace nvcuda;

#define B_ 32
#define L_ 720
#define N_ 512
#define H_ 16
#define D_ 64
#define TOPK_ 8
#define M_ (B_*L_)   // 23040

// ---------------- scratch (static device memory; no allocations) ----------------
__device__ int   g_idx[N_*TOPK_];
__device__ float g_w[N_*TOPK_];
__device__ float g_center[B_*N_];
__device__ float g_cg[B_*N_];
__device__ __align__(16) float g_ring[(size_t)M_*N_];
__device__ __align__(16) float g_fused[(size_t)M_*N_];
__device__ __align__(16) float g_h[(size_t)M_*N_];

// ---------------- 1. fused center pipeline: score + softmax + csum + MLP + cg ---------
// one block per batch, 256 threads
__global__ __launch_bounds__(256) void center_fused(const float* __restrict__ x,
                                                    const float* __restrict__ Wscore,
                                                    const float* __restrict__ bscore,
                                                    const float* __restrict__ Wc1,
                                                    const float* __restrict__ bc1,
                                                    const float* __restrict__ Wc2,
                                                    const float* __restrict__ bc2,
                                                    const float* __restrict__ Wcn,
                                                    const float* __restrict__ bcn,
                                                    const float* __restrict__ Wg) {
    int b = blockIdx.x, tid = threadIdx.x;
    int w = tid >> 5, lane = tid & 31;
    __shared__ float p[L_];
    __shared__ float red[256];
    __shared__ float cr[N_];
    __shared__ float c1[D_];
    __shared__ float c2[D_];
    __shared__ float ctr[N_];
    const float* xb = x + (size_t)b*L_*N_;

    // --- score logits (warp per row, lane-parallel dot) ---
    for (int l = w; l < L_; l += 8) {
        const float4* xr = (const float4*)(xb + (size_t)l*N_);
        const float4* wr = (const float4*)Wscore;
        float s = 0.f;
#pragma unroll
        for (int c = 0; c < 4; c++) {
            float4 v = xr[lane + c*32], ww = wr[lane + c*32];
            s += v.x*ww.x + v.y*ww.y + v.z*ww.z + v.w*ww.w;
        }
#pragma unroll
        for (int o = 16; o > 0; o >>= 1) s += __shfl_xor_sync(0xffffffffu, s, o);
        if (lane == 0) p[l] = s + bscore[0];
    }
    __syncthreads();

    // --- softmax over L ---
    float m = -1e30f;
    for (int l = tid; l < L_; l += 256) m = fmaxf(m, p[l]);
    red[tid] = m; __syncthreads();
    for (int o = 128; o > 0; o >>= 1) { if (tid < o) red[tid] = fmaxf(red[tid], red[tid+o]); __syncthreads(); }
    m = red[0]; __syncthreads();
    float s = 0.f;
    for (int l = tid; l < L_; l += 256) { float e = expf(p[l]-m); p[l] = e; s += e; }
    red[tid] = s; __syncthreads();
    for (int o = 128; o > 0; o >>= 1) { if (tid < o) red[tid] += red[tid+o]; __syncthreads(); }
    float inv = 1.f/red[0];
    __syncthreads();
    for (int l = tid; l < L_; l += 256) p[l] *= inv;
    __syncthreads();

    // --- weighted sum over L -> cr ---
    for (int c = tid; c < N_; c += 256) {
        float acc = 0.f;
        for (int l = 0; l < L_; l++) acc += p[l]*xb[(size_t)l*N_+c];
        cr[c] = acc;
    }
    __syncthreads();

    // --- MLP ---
    {
        int d = tid >> 2, part = tid & 3;
        float t = 0.f;
        for (int n = part*128; n < part*128+128; n++) t += cr[n]*Wc1[n*D_+d];
        t += __shfl_xor_sync(0xffffffffu, t, 1);
        t += __shfl_xor_sync(0xffffffffu, t, 2);
        if (part == 0) {
            t += bc1[d];
            c1[d] = 0.5f*t*(1.f + erff(t*0.7071067811865475f));
        }
    }
    __syncthreads();
    if (tid < D_) {
        float t = bc2[tid];
#pragma unroll
        for (int e = 0; e < D_; e++) t += c1[e]*Wc2[e*D_+tid];
        c2[tid] = 0.5f*t*(1.f + erff(t*0.7071067811865475f));
    }
    __syncthreads();
    for (int n = tid; n < N_; n += 256) {
        float t = bcn[n];
#pragma unroll
        for (int d = 0; d < D_; d++) t += c2[d]*Wcn[d*N_+n];
        ctr[n] = t;
        g_center[b*N_+n] = t;
    }
    __syncthreads();

    // --- cg = center @ Wg[N:2N] ---
    for (int n2 = tid; n2 < N_; n2 += 256) {
        float t = 0.f;
        for (int n = 0; n < N_; n++) t += ctr[n]*Wg[(size_t)(N_+n)*N_ + n2];
        g_cg[b*N_+n2] = t;
    }
}

// ---------------- 2. fused QK + top-8 + softmax weights ----------------
__global__ __launch_bounds__(128) void topk_fused(const float* __restrict__ ve,
                                                  const float* __restrict__ Wq,
                                                  const float* __restrict__ bq,
                                                  const float* __restrict__ Wk,
                                                  const float* __restrict__ bk) {
    int n = blockIdx.x, tid = threadIdx.x;   // 128 threads
    __shared__ float Kmat[N_][H_];
    __shared__ float sim[N_];
    __shared__ float q[H_];
    __shared__ float rv[128];
    __shared__ int   ri[128];
    __shared__ float tv[TOPK_];
    __shared__ int   tix[TOPK_];

    // K rows (4 per thread)
    for (int mm = tid; mm < N_; mm += 128) {
        float v[H_];
#pragma unroll
        for (int j = 0; j < H_; j++) v[j] = ve[mm*H_+j];
#pragma unroll
        for (int h = 0; h < H_; h++) {
            float k = bk[h];
#pragma unroll
            for (int j = 0; j < H_; j++) k += v[j]*Wk[j*H_+h];
            Kmat[mm][h] = k;
        }
    }
    // Q row n
    if (tid < H_) {
        float qv = bq[tid];
#pragma unroll
        for (int j = 0; j < H_; j++) qv += ve[n*H_+j]*Wq[j*H_+tid];
        q[tid] = qv;
    }
    __syncthreads();

    for (int m = tid; m < N_; m += 128) {
        float s = 0.f;
#pragma unroll
        for (int j = 0; j < H_; j++) s += q[j]*Kmat[m][j];
        sim[m] = (m == n) ? -1e9f : s;
    }
    __syncthreads();

    for (int t = 0; t < TOPK_; t++) {
        float bv = -1e30f; int bi = 0x7fffffff;
        for (int m = tid; m < N_; m += 128) {
            float s = sim[m];
            if (s > bv) { bv = s; bi = m; }
        }
        rv[tid] = bv; ri[tid] = bi;
        __syncthreads();
        for (int off = 64; off > 0; off >>= 1) {
            if (tid < off) {
                float ov = rv[tid+off]; int oi = ri[tid+off];
                if (ov > rv[tid] || (ov == rv[tid] && oi < ri[tid])) { rv[tid] = ov; ri[tid] = oi; }
            }
            __syncthreads();
        }
        if (tid == 0) { tv[t] = rv[0]; tix[t] = ri[0]; sim[ri[0]] = -1e30f; }
        __syncthreads();
    }
    if (tid == 0) {
        float mx = tv[0], e[TOPK_], s = 0.f;
#pragma unroll
        for (int t = 0; t < TOPK_; t++) { e[t] = expf(tv[t]-mx); s += e[t]; }
        float inv = 1.f/s;
#pragma unroll
        for (int t = 0; t < TOPK_; t++) { g_w[n*TOPK_+t] = e[t]*inv; g_idx[n*TOPK_+t] = tix[t]; }
    }
}

// ---------------- 3. ring gather ----------------
#define TL 8
__global__ void ring_kernel(const float* __restrict__ x) {
    int b = blockIdx.y, l0 = blockIdx.x * TL, tid = threadIdx.x;   // 256 threads
    __shared__ float xt[TL][N_];
    const float* xb = x + (size_t)b*L_*N_ + (size_t)l0*N_;
    for (int i = tid; i < TL*N_/4; i += 256)
        ((float4*)xt)[i] = ((const float4*)xb)[i];
    __syncthreads();
    float* outb = g_ring + (size_t)b*L_*N_ + (size_t)l0*N_;
    for (int o = tid; o < TL*N_; o += 256) {
        int l = o >> 9, n = o & 511;
        float acc = 0.f;
#pragma unroll
        for (int k = 0; k < TOPK_; k++) {
            int id  = __ldg(&g_idx[n*TOPK_+k]);
            float w = __ldg(&g_w[n*TOPK_+k]);
            acc += xt[l][id] * w;
        }
        outb[o] = acc;
    }
}

// ---------------- 4. WMMA tf32 GEMM, R6 serial structure, cvt in staging -------------
// C = A @ W   (A: M x 512 fp32 row-major; W: 512 x 512 fp32 row-major used directly)
// mode 0: A=g_ring,  W=Wg(top rows);  epi: sigmoid gate mix -> g_fused (fp32)
// mode 1: A=g_fused, W=Wf;            epi: raw product -> g_h (bias+residual in ln)
#define BM_ 128
#define BN_ 128
#define BK_ 32
#define A_LDF 36     // fp32 elems per A smem row (32 + 4 pad)
#define W_LDF 132    // fp32 elems per W smem row (128 + 4 pad)
#define SA_OFF 0
#define SW_OFF 18432                 // 128*36*4
#define GEMM_SMEM_ 35328             // + 32*132*4 = 16896
#define STG_LD 68    // fp32 staging row stride (epilogue: 8*16*68*4 = 34816 <= 35328)

__global__ __launch_bounds__(256) void gemm_wmma(int mode,
                                                 const float* __restrict__ Wmat,
                                                 const float* __restrict__ e0) {
    extern __shared__ __align__(128) char smem[];
    const int tid = threadIdx.x, wid = tid >> 5, lane = tid & 31;
    const int wm = wid >> 1, wn = wid & 1;   // warp grid 4(m) x 2(n): warp tile 32 x 64
    const int row0 = blockIdx.x * BM_, col0 = blockIdx.y * BN_;

    const float* A = (mode == 0) ? g_ring : g_fused;

    float* sA = (float*)(smem + SA_OFF);
    float* sW = (float*)(smem + SW_OFF);

    wmma::fragment<wmma::accumulator, 16, 16, 8, float> facc[2][4];
#pragma unroll
    for (int mi = 0; mi < 2; mi++)
#pragma unroll
        for (int p = 0; p < 4; p++) wmma::fill_fragment(facc[mi][p], 0.f);

    const int NKB = N_ / BK_;   // 16
    for (int kb = 0; kb < NKB; kb++) {
        const int k0 = kb * BK_;
        __syncthreads();   // protect smem from previous iteration's readers
        // --- A tile: 128 x 32 fp32, tf32-round in staging. 1024 float4 chunks, 4/thread.
#pragma unroll
        for (int i = 0; i < 4; i++) {
            int c = i*256 + tid;
            int row = c >> 3, col4 = (c & 7) * 4;
            float4 v = *(const float4*)(A + (size_t)(row0+row)*N_ + k0 + col4);
            v.x = wmma::__float_to_tf32(v.x);
            v.y = wmma::__float_to_tf32(v.y);
            v.z = wmma::__float_to_tf32(v.z);
            v.w = wmma::__float_to_tf32(v.w);
            *(float4*)(sA + row*A_LDF + col4) = v;
        }
        // --- W tile: 32 x 128 fp32. 1024 float4 chunks, 4/thread.
#pragma unroll
        for (int i = 0; i < 4; i++) {
            int c = i*256 + tid;
            int row = c >> 5, col4 = (c & 31) * 4;
            float4 v = *(const float4*)(Wmat + (size_t)(k0+row)*N_ + col0 + col4);
            v.x = wmma::__float_to_tf32(v.x);
            v.y = wmma::__float_to_tf32(v.y);
            v.z = wmma::__float_to_tf32(v.z);
            v.w = wmma::__float_to_tf32(v.w);
            *(float4*)(sW + row*W_LDF + col4) = v;
        }
        __syncthreads();

#pragma unroll
        for (int ks = 0; ks < 4; ks++) {    // 4 x K=8
            wmma::fragment<wmma::matrix_a, 16, 16, 8, wmma::precision::tf32, wmma::row_major> fa[2];
#pragma unroll
            for (int mi = 0; mi < 2; mi++)
                wmma::load_matrix_sync(fa[mi], sA + (wm*32 + mi*16)*A_LDF + ks*8, A_LDF);
#pragma unroll
            for (int p = 0; p < 4; p++) {
                wmma::fragment<wmma::matrix_b, 16, 16, 8, wmma::precision::tf32, wmma::row_major> fb;
                wmma::load_matrix_sync(fb, sW + (ks*8)*W_LDF + wn*64 + p*16, W_LDF);
#pragma unroll
                for (int mi = 0; mi < 2; mi++)
                    wmma::mma_sync(facc[mi][p], fa[mi], fb, facc[mi][p]);
            }
        }
    }
    __syncthreads();   // all compute done before smem reuse as staging

    if (mode == 1) {
#pragma unroll
        for (int mi = 0; mi < 2; mi++)
#pragma unroll
            for (int p = 0; p < 4; p++) {
                float* dst = g_h + (size_t)(row0 + wm*32 + mi*16)*N_ + col0 + wn*64 + p*16;
                wmma::store_matrix_sync(dst, facc[mi][p], N_, wmma::mem_row_major);
            }
        return;
    }

    // ---- mode 0 epilogue: two passes of 16 rows via per-warp smem staging ----
    float* wst = (float*)smem + wid * (16 * STG_LD);
#pragma unroll
    for (int mi = 0; mi < 2; mi++) {
#pragma unroll
        for (int p = 0; p < 4; p++)
            wmma::store_matrix_sync(wst + p*16, facc[mi][p], STG_LD, wmma::mem_row_major);
        __syncwarp();
        int r16 = lane >> 1;
        int coff = (lane & 1) * 32;
        int r = row0 + wm*32 + mi*16 + r16;
        int bb = r / L_;
        size_t rb = (size_t)r * N_;
        const float* myrow = wst + r16*STG_LD + coff;
#pragma unroll
        for (int q = 0; q < 8; q++) {
            float4 v = *(const float4*)(myrow + q*4);
            int c = col0 + wn*64 + coff + q*4;
            float4 o;
#pragma unroll
            for (int t = 0; t < 4; t++) {
                int cc = c + t;
                float vv = (&v.x)[t];
                float pre = vv + g_cg[bb*N_+cc] + e0[cc];
                float g = 1.f/(1.f + expf(-pre));
                float rv = g_ring[rb+cc];
                (&o.x)[t] = g*rv + (1.f-g)*g_center[bb*N_+cc];
            }
            *(float4*)(g_fused + rb + c) = o;
        }
        __syncwarp();
    }
}

// ---------------- 5. LayerNorm over N (+ folded Wf bias and residual) ----------------
__global__ void ln_kernel(const float* __restrict__ gamma, const float* __restrict__ beta,
                          const float* __restrict__ bf, const float* __restrict__ x,
                          float* __restrict__ out) {
    int r = blockIdx.x, tid = threadIdx.x;   // 256 threads
    size_t base = (size_t)r*N_;
    float a  = g_h[base+tid]     + bf[tid]     + x[base+tid];
    float b2 = g_h[base+tid+256] + bf[tid+256] + x[base+tid+256];
    __shared__ float rs[256], rq[256];
    rs[tid] = a + b2;
    rq[tid] = a*a + b2*b2;
    __syncthreads();
    for (int o = 128; o > 0; o >>= 1) {
        if (tid < o) { rs[tid] += rs[tid+o]; rq[tid] += rq[tid+o]; }
        __syncthreads();
    }
    float mu  = rs[0] * (1.f/N_);
    float var = rq[0] * (1.f/N_) - mu*mu;
    float inv = rsqrtf(var + 1e-5f);
    out[base+tid]     = (a  - mu)*inv*gamma[tid]     + beta[tid];
    out[base+tid+256] = (b2 - mu)*inv*gamma[tid+256] + beta[tid+256];
}

// ---------------- launch ----------------
extern "C" void kernel_launch(void* const* d_in, const int* in_sizes, int n_in,
                              void* d_out, int out_size) {
    const float* x      = (const float*)d_in[0];
    const float* ve     = (const float*)d_in[1];
    const float* Wq     = (const float*)d_in[2];
    const float* bq     = (const float*)d_in[3];
    const float* Wk     = (const float*)d_in[4];
    const float* bk     = (const float*)d_in[5];
    const float* Wscore = (const float*)d_in[6];
    const float* bscore = (const float*)d_in[7];
    const float* Wc1    = (const float*)d_in[8];
    const float* bc1    = (const float*)d_in[9];
    const float* Wc2    = (const float*)d_in[10];
    const float* bc2    = (const float*)d_in[11];
    const float* Wcn    = (const float*)d_in[12];
    const float* bcn    = (const float*)d_in[13];
    const float* Wg     = (const float*)d_in[14];
    const float* bg     = (const float*)d_in[15];
    const float* Wf     = (const float*)d_in[16];
    const float* bf     = (const float*)d_in[17];
    const float* gamma  = (const float*)d_in[18];
    const float* beta   = (const float*)d_in[19];
    float* out = (float*)d_out;

    cudaFuncSetAttribute(gemm_wmma, cudaFuncAttributeMaxDynamicSharedMemorySize, GEMM_SMEM_);

    center_fused<<<B_, 256>>>(x, Wscore, bscore, Wc1, bc1, Wc2, bc2, Wcn, bcn, Wg);  // #0
    topk_fused<<<N_, 128>>>(ve, Wq, bq, Wk, bk);                                      // #1
    ring_kernel<<<dim3(L_/TL, B_), 256>>>(x);                                         // #2
    gemm_wmma<<<dim3(M_/BM_, N_/BN_), 256, GEMM_SMEM_>>>(0, Wg, bg);                  // #3 <- profiled
    gemm_wmma<<<dim3(M_/BM_, N_/BN_), 256, GEMM_SMEM_>>>(1, Wf, nullptr);             // #4
    ln_kernel<<<M_, 256>>>(gamma, beta, bf, x, out);                                  // #5
}

// round 11
// speedup vs baseline: 1.0727x; 1.0432x over previous
#include <cuda_runtime.h>
#include <cuda_bf16.h>
#include <mma.h>
#include <math.h>
#include <stdint.h>

using namespace nvcuda;

#define B_ 32
#define L_ 720
#define N_ 512
#define H_ 16
#define D_ 64
#define TOPK_ 8
#define M_ (B_*L_)   // 23040

// ---------------- scratch (static device memory; no allocations) ----------------
__device__ int   g_idx[N_*TOPK_];
__device__ float g_w[N_*TOPK_];
__device__ float g_logit[B_*L_];
__device__ float g_center_raw[B_*N_];
__device__ float g_center[B_*N_];
__device__ float g_cg[B_*N_];
__device__ __align__(16) float g_ring[(size_t)M_*N_];
__device__ __align__(16) float g_fused[(size_t)M_*N_];
__device__ __align__(16) float g_h[(size_t)M_*N_];

// ---------------- helpers ----------------
__device__ __forceinline__ uint32_t smem_to_u32(const void* p) {
    uint32_t a;
    asm("{ .reg .u64 t; cvta.to.shared.u64 t, %1; cvt.u32.u64 %0, t; }" : "=r"(a) : "l"(p));
    return a;
}
__device__ __forceinline__ void cpa16(uint32_t d, const void* s) {
    asm volatile("cp.async.cg.shared.global [%0], [%1], 16;" :: "r"(d), "l"(s) : "memory");
}
#define CP_COMMIT() asm volatile("cp.async.commit_group;" ::: "memory")
#define CP_WAIT1()  asm volatile("cp.async.wait_group 1;" ::: "memory")
#define CP_WAIT0()  asm volatile("cp.async.wait_group 0;" ::: "memory")

// ---------------- 1. fused QK + top-8 + softmax weights ----------------
__global__ __launch_bounds__(128) void topk_fused(const float* __restrict__ ve,
                                                  const float* __restrict__ Wq,
                                                  const float* __restrict__ bq,
                                                  const float* __restrict__ Wk,
                                                  const float* __restrict__ bk) {
    int n = blockIdx.x, tid = threadIdx.x;   // 128 threads
    __shared__ float Kmat[N_][H_];
    __shared__ float sim[N_];
    __shared__ float q[H_];
    __shared__ float rv[128];
    __shared__ int   ri[128];
    __shared__ float tv[TOPK_];
    __shared__ int   tix[TOPK_];

    for (int mm = tid; mm < N_; mm += 128) {
        float v[H_];
#pragma unroll
        for (int j = 0; j < H_; j++) v[j] = ve[mm*H_+j];
#pragma unroll
        for (int h = 0; h < H_; h++) {
            float k = bk[h];
#pragma unroll
            for (int j = 0; j < H_; j++) k += v[j]*Wk[j*H_+h];
            Kmat[mm][h] = k;
        }
    }
    if (tid < H_) {
        float qv = bq[tid];
#pragma unroll
        for (int j = 0; j < H_; j++) qv += ve[n*H_+j]*Wq[j*H_+tid];
        q[tid] = qv;
    }
    __syncthreads();

    for (int m = tid; m < N_; m += 128) {
        float s = 0.f;
#pragma unroll
        for (int j = 0; j < H_; j++) s += q[j]*Kmat[m][j];
        sim[m] = (m == n) ? -1e9f : s;
    }
    __syncthreads();

    for (int t = 0; t < TOPK_; t++) {
        float bv = -1e30f; int bi = 0x7fffffff;
        for (int m = tid; m < N_; m += 128) {
            float s = sim[m];
            if (s > bv) { bv = s; bi = m; }
        }
        rv[tid] = bv; ri[tid] = bi;
        __syncthreads();
        for (int off = 64; off > 0; off >>= 1) {
            if (tid < off) {
                float ov = rv[tid+off]; int oi = ri[tid+off];
                if (ov > rv[tid] || (ov == rv[tid] && oi < ri[tid])) { rv[tid] = ov; ri[tid] = oi; }
            }
            __syncthreads();
        }
        if (tid == 0) { tv[t] = rv[0]; tix[t] = ri[0]; sim[ri[0]] = -1e30f; }
        __syncthreads();
    }
    if (tid == 0) {
        float mx = tv[0], e[TOPK_], s = 0.f;
#pragma unroll
        for (int t = 0; t < TOPK_; t++) { e[t] = expf(tv[t]-mx); s += e[t]; }
        float inv = 1.f/s;
#pragma unroll
        for (int t = 0; t < TOPK_; t++) { g_w[n*TOPK_+t] = e[t]*inv; g_idx[n*TOPK_+t] = tix[t]; }
    }
}

// ---------------- 2. score logits ----------------
__global__ void score_kernel(const float* __restrict__ x,
                             const float* __restrict__ Wscore,
                             const float* __restrict__ bscore) {
    int b = blockIdx.y, l0 = blockIdx.x * 90;
    int w = threadIdx.x >> 5, lane = threadIdx.x & 31;
    for (int l = l0 + w; l < l0 + 90; l += 8) {
        const float4* xr = (const float4*)(x + ((size_t)b*L_+l)*N_);
        const float4* wr = (const float4*)Wscore;
        float s = 0.f;
#pragma unroll
        for (int c = 0; c < 4; c++) {
            float4 v = xr[lane + c*32], ww = wr[lane + c*32];
            s += v.x*ww.x + v.y*ww.y + v.z*ww.z + v.w*ww.w;
        }
#pragma unroll
        for (int o = 16; o > 0; o >>= 1) s += __shfl_xor_sync(0xffffffffu, s, o);
        if (lane == 0) g_logit[b*L_+l] = s + bscore[0];
    }
}

// ---------------- 3. fused softmax-over-L + weighted sum (128 blocks) ----------------
__global__ void csum_kernel(const float* __restrict__ x) {
    int b = blockIdx.y, c = blockIdx.x*128 + threadIdx.x;
    int tid = threadIdx.x;   // 128 threads
    __shared__ float p[L_];
    __shared__ float red[128];
    for (int l = tid; l < L_; l += 128) p[l] = g_logit[b*L_+l];
    __syncthreads();
    float m = -1e30f;
    for (int l = tid; l < L_; l += 128) m = fmaxf(m, p[l]);
    red[tid] = m; __syncthreads();
    for (int o = 64; o > 0; o >>= 1) { if (tid < o) red[tid] = fmaxf(red[tid], red[tid+o]); __syncthreads(); }
    m = red[0]; __syncthreads();
    float s = 0.f;
    for (int l = tid; l < L_; l += 128) { float e = expf(p[l]-m); p[l] = e; s += e; }
    red[tid] = s; __syncthreads();
    for (int o = 64; o > 0; o >>= 1) { if (tid < o) red[tid] += red[tid+o]; __syncthreads(); }
    float inv = 1.f/red[0];
    __syncthreads();
    for (int l = tid; l < L_; l += 128) p[l] *= inv;
    __syncthreads();
    float acc = 0.f;
    const float* xb = x + (size_t)b*L_*N_ + c;
    for (int l = 0; l < L_; l++) acc += p[l]*xb[(size_t)l*N_];
    g_center_raw[b*N_+c] = acc;
}

// ---------------- 4a. center MLP ----------------
__global__ void mlp_kernel(const float* __restrict__ Wc1, const float* __restrict__ bc1,
                           const float* __restrict__ Wc2, const float* __restrict__ bc2,
                           const float* __restrict__ Wcn, const float* __restrict__ bcn) {
    int b = blockIdx.x, tid = threadIdx.x;   // 256 threads
    __shared__ float cr[N_];
    __shared__ float c1[D_];
    __shared__ float c2[D_];
    for (int n = tid; n < N_; n += 256) cr[n] = g_center_raw[b*N_+n];
    __syncthreads();
    {
        int d = tid >> 2, part = tid & 3;
        float s = 0.f;
        for (int n = part*128; n < part*128+128; n++) s += cr[n]*Wc1[n*D_+d];
        s += __shfl_xor_sync(0xffffffffu, s, 1);
        s += __shfl_xor_sync(0xffffffffu, s, 2);
        if (part == 0) {
            s += bc1[d];
            c1[d] = 0.5f*s*(1.f + erff(s*0.7071067811865475f));
        }
    }
    __syncthreads();
    if (tid < D_) {
        float s = bc2[tid];
#pragma unroll
        for (int e = 0; e < D_; e++) s += c1[e]*Wc2[e*D_+tid];
        c2[tid] = 0.5f*s*(1.f + erff(s*0.7071067811865475f));
    }
    __syncthreads();
    for (int n = tid; n < N_; n += 256) {
        float s = bcn[n];
#pragma unroll
        for (int d = 0; d < D_; d++) s += c2[d]*Wcn[d*N_+n];
        g_center[b*N_+n] = s;
    }
}

// ---------------- 4b. cg = center @ Wg[N:2N] ----------------
__global__ void cg_kernel(const float* __restrict__ Wg) {
    int b = blockIdx.x, n2 = blockIdx.y*128 + threadIdx.x;
    __shared__ float ctr[N_];
    for (int n = threadIdx.x; n < N_; n += 128) ctr[n] = g_center[b*N_+n];
    __syncthreads();
    float s = 0.f;
    for (int n = 0; n < N_; n++) s += ctr[n]*Wg[(size_t)(N_+n)*N_ + n2];
    g_cg[b*N_+n2] = s;
}

// ---------------- 5. ring gather ----------------
#define TL 8
__global__ void ring_kernel(const float* __restrict__ x) {
    int b = blockIdx.y, l0 = blockIdx.x * TL, tid = threadIdx.x;   // 256 threads
    __shared__ float xt[TL][N_];
    const float* xb = x + (size_t)b*L_*N_ + (size_t)l0*N_;
    for (int i = tid; i < TL*N_/4; i += 256)
        ((float4*)xt)[i] = ((const float4*)xb)[i];
    __syncthreads();
    float* outb = g_ring + (size_t)b*L_*N_ + (size_t)l0*N_;
    for (int o = tid; o < TL*N_; o += 256) {
        int l = o >> 9, n = o & 511;
        float acc = 0.f;
#pragma unroll
        for (int k = 0; k < TOPK_; k++) {
            int id  = __ldg(&g_idx[n*TOPK_+k]);
            float w = __ldg(&g_w[n*TOPK_+k]);
            acc += xt[l][id] * w;
        }
        outb[o] = acc;
    }
}

// ---------------- 6. WMMA tf32 GEMM: 128x128 CTA, 4 warps (64x64/warp), cp.async -----
// HW rounds fp32->tf32 inside the tensor core; staging is a pure async copy.
// mode 0: A=g_ring,  W=Wg(top rows);  epi: sigmoid gate mix -> g_fused (fp32)
// mode 1: A=g_fused, W=Wf;            epi: raw product -> g_h (bias+residual in ln)
#define BM_ 128
#define BN_ 128
#define BK_ 32
#define A_LDF 36     // fp32 elems per A smem row (32 + 4 pad)
#define W_LDF 132    // fp32 elems per W smem row (128 + 4 pad)
#define SA_OFF 0
#define SW_OFF 18432                 // 128*36*4
#define BUF_B_ 35328                 // + 32*132*4
#define GEMM_SMEM_ (2*BUF_B_)        // 70656
#define STG_LD 68    // fp32 staging row stride (epi: 4 warps * 16*68*4 = 17408 B)

__global__ __launch_bounds__(128) void gemm_wmma(int mode,
                                                 const float* __restrict__ Wmat,
                                                 const float* __restrict__ e0) {
    extern __shared__ __align__(128) char smem[];
    const int tid = threadIdx.x, wid = tid >> 5, lane = tid & 31;
    const int wm = wid >> 1, wn = wid & 1;   // warp grid 2x2: warp tile 64 x 64
    const int row0 = blockIdx.x * BM_, col0 = blockIdx.y * BN_;
    const uint32_t sbase = smem_to_u32(smem);

    const float* A = (mode == 0) ? g_ring : g_fused;

    wmma::fragment<wmma::accumulator, 16, 16, 8, float> facc[4][4];
#pragma unroll
    for (int mi = 0; mi < 4; mi++)
#pragma unroll
        for (int p = 0; p < 4; p++) wmma::fill_fragment(facc[mi][p], 0.f);

    // cp.async staging: A 128x32 (1024 float4) + W 32x128 (1024 float4), 16/thread
    auto issue = [&](int kb, int buf) {
        const int k0 = kb * BK_;
        const uint32_t bb = sbase + (uint32_t)buf * BUF_B_;
#pragma unroll
        for (int i = 0; i < 8; i++) {       // A chunks
            int c = i*128 + tid;
            int row = c >> 3, col4 = (c & 7) * 4;
            cpa16(bb + SA_OFF + (uint32_t)(row*A_LDF + col4)*4,
                  A + (size_t)(row0+row)*N_ + k0 + col4);
        }
#pragma unroll
        for (int i = 0; i < 8; i++) {       // W chunks
            int c = i*128 + tid;
            int row = c >> 5, col4 = (c & 31) * 4;
            cpa16(bb + SW_OFF + (uint32_t)(row*W_LDF + col4)*4,
                  Wmat + (size_t)(k0+row)*N_ + col0 + col4);
        }
        CP_COMMIT();
    };

    const int NKB = N_ / BK_;   // 16
    issue(0, 0);
    for (int kb = 0; kb < NKB; kb++) {
        const int buf = kb & 1;
        if (kb + 1 < NKB) { issue(kb + 1, buf ^ 1); CP_WAIT1(); }
        else              { CP_WAIT0(); }
        __syncthreads();

        const char* bb = smem + buf * BUF_B_;
        const float* sA = (const float*)(bb + SA_OFF);
        const float* sW = (const float*)(bb + SW_OFF);

#pragma unroll
        for (int ks = 0; ks < 4; ks++) {    // 4 x K=8
            wmma::fragment<wmma::matrix_a, 16, 16, 8, wmma::precision::tf32, wmma::row_major> fa[4];
#pragma unroll
            for (int mi = 0; mi < 4; mi++)
                wmma::load_matrix_sync(fa[mi], sA + (wm*64 + mi*16)*A_LDF + ks*8, A_LDF);
#pragma unroll
            for (int p = 0; p < 4; p++) {
                wmma::fragment<wmma::matrix_b, 16, 16, 8, wmma::precision::tf32, wmma::row_major> fb;
                wmma::load_matrix_sync(fb, sW + (ks*8)*W_LDF + wn*64 + p*16, W_LDF);
#pragma unroll
                for (int mi = 0; mi < 4; mi++)
                    wmma::mma_sync(facc[mi][p], fa[mi], fb, facc[mi][p]);
            }
        }
        __syncthreads();   // MMA(kb) done before issue(kb+2) overwrites this buf
    }

    if (mode == 1) {
#pragma unroll
        for (int mi = 0; mi < 4; mi++)
#pragma unroll
            for (int p = 0; p < 4; p++) {
                float* dst = g_h + (size_t)(row0 + wm*64 + mi*16)*N_ + col0 + wn*64 + p*16;
                wmma::store_matrix_sync(dst, facc[mi][p], N_, wmma::mem_row_major);
            }
        return;
    }

    // ---- mode 0 epilogue: 4 passes of 16 rows via per-warp smem staging ----
    float* wst = (float*)smem + wid * (16 * STG_LD);
#pragma unroll
    for (int mi = 0; mi < 4; mi++) {
#pragma unroll
        for (int p = 0; p < 4; p++)
            wmma::store_matrix_sync(wst + p*16, facc[mi][p], STG_LD, wmma::mem_row_major);
        __syncwarp();
        int r16 = lane >> 1;
        int coff = (lane & 1) * 32;
        int r = row0 + wm*64 + mi*16 + r16;
        int bb = r / L_;
        size_t rb = (size_t)r * N_;
        const float* myrow = wst + r16*STG_LD + coff;
#pragma unroll
        for (int q = 0; q < 8; q++) {
            float4 v = *(const float4*)(myrow + q*4);
            int c = col0 + wn*64 + coff + q*4;
            float4 o;
#pragma unroll
            for (int t = 0; t < 4; t++) {
                int cc = c + t;
                float vv = (&v.x)[t];
                float pre = vv + g_cg[bb*N_+cc] + e0[cc];
                float g = 1.f/(1.f + expf(-pre));
                float rv = g_ring[rb+cc];
                (&o.x)[t] = g*rv + (1.f-g)*g_center[bb*N_+cc];
            }
            *(float4*)(g_fused + rb + c) = o;
        }
        __syncwarp();
    }
}

// ---------------- 7. LayerNorm over N (+ folded Wf bias and residual) ----------------
__global__ void ln_kernel(const float* __restrict__ gamma, const float* __restrict__ beta,
                          const float* __restrict__ bf, const float* __restrict__ x,
                          float* __restrict__ out) {
    int r = blockIdx.x, tid = threadIdx.x;   // 256 threads
    size_t base = (size_t)r*N_;
    float a  = g_h[base+tid]     + bf[tid]     + x[base+tid];
    float b2 = g_h[base+tid+256] + bf[tid+256] + x[base+tid+256];
    __shared__ float rs[256], rq[256];
    rs[tid] = a + b2;
    rq[tid] = a*a + b2*b2;
    __syncthreads();
    for (int o = 128; o > 0; o >>= 1) {
        if (tid < o) { rs[tid] += rs[tid+o]; rq[tid] += rq[tid+o]; }
        __syncthreads();
    }
    float mu  = rs[0] * (1.f/N_);
    float var = rq[0] * (1.f/N_) - mu*mu;
    float inv = rsqrtf(var + 1e-5f);
    out[base+tid]     = (a  - mu)*inv*gamma[tid]     + beta[tid];
    out[base+tid+256] = (b2 - mu)*inv*gamma[tid+256] + beta[tid+256];
}

// ---------------- launch ----------------
extern "C" void kernel_launch(void* const* d_in, const int* in_sizes, int n_in,
                              void* d_out, int out_size) {
    const float* x      = (const float*)d_in[0];
    const float* ve     = (const float*)d_in[1];
    const float* Wq     = (const float*)d_in[2];
    const float* bq     = (const float*)d_in[3];
    const float* Wk     = (const float*)d_in[4];
    const float* bk     = (const float*)d_in[5];
    const float* Wscore = (const float*)d_in[6];
    const float* bscore = (const float*)d_in[7];
    const float* Wc1    = (const float*)d_in[8];
    const float* bc1    = (const float*)d_in[9];
    const float* Wc2    = (const float*)d_in[10];
    const float* bc2    = (const float*)d_in[11];
    const float* Wcn    = (const float*)d_in[12];
    const float* bcn    = (const float*)d_in[13];
    const float* Wg     = (const float*)d_in[14];
    const float* bg     = (const float*)d_in[15];
    const float* Wf     = (const float*)d_in[16];
    const float* bf     = (const float*)d_in[17];
    const float* gamma  = (const float*)d_in[18];
    const float* beta   = (const float*)d_in[19];
    float* out = (float*)d_out;

    cudaFuncSetAttribute(gemm_wmma, cudaFuncAttributeMaxDynamicSharedMemorySize, GEMM_SMEM_);

    topk_fused<<<N_, 128>>>(ve, Wq, bq, Wk, bk);                          // #0
    score_kernel<<<dim3(8, B_), 256>>>(x, Wscore, bscore);                // #1
    ring_kernel<<<dim3(L_/TL, B_), 256>>>(x);                             // #2
    csum_kernel<<<dim3(4, B_), 128>>>(x);                                 // #3 <- profiled (known)
    mlp_kernel<<<B_, 256>>>(Wc1, bc1, Wc2, bc2, Wcn, bcn);                // #4
    cg_kernel<<<dim3(B_, 4), 128>>>(Wg);                                  // #5
    gemm_wmma<<<dim3(M_/BM_, N_/BN_), 128, GEMM_SMEM_>>>(0, Wg, bg);      // #6
    gemm_wmma<<<dim3(M_/BM_, N_/BN_), 128, GEMM_SMEM_>>>(1, Wf, nullptr); // #7
    ln_kernel<<<M_, 256>>>(gamma, beta, bf, x, out);                      // #8
}

// round 12
// speedup vs baseline: 1.1163x; 1.0406x over previous
#include <cuda_runtime.h>
#include <cuda_bf16.h>
#include <mma.h>
#include <math.h>
#include <stdint.h>

using namespace nvcuda;

#define B_ 32
#define L_ 720
#define N_ 512
#define H_ 16
#define D_ 64
#define TOPK_ 8
#define M_ (B_*L_)   // 23040

// ---------------- scratch (static device memory; no allocations) ----------------
__device__ float g_Q[N_*H_];
__device__ float g_K[N_*H_];
__device__ int   g_idx[N_*TOPK_];
__device__ float g_w[N_*TOPK_];
__device__ float g_logit[B_*L_];
__device__ float g_center_raw[B_*N_];
__device__ float g_center[B_*N_];
__device__ float g_cg[B_*N_];
__device__ float g_ring[(size_t)M_*N_];
__device__ float g_fused[(size_t)M_*N_];
__device__ float g_h[(size_t)M_*N_];

// ---------------- helpers ----------------
__device__ __forceinline__ void bsplit(float v, __nv_bfloat16& h, __nv_bfloat16& l) {
    h = __float2bfloat16(v);
    l = __float2bfloat16(v - __bfloat162float(h));
}

// ---------------- 1. Q/K projection ----------------
__global__ void qk_kernel(const float* __restrict__ ve,
                          const float* __restrict__ Wq, const float* __restrict__ bq,
                          const float* __restrict__ Wk, const float* __restrict__ bk) {
    int n = blockIdx.x * blockDim.x + threadIdx.x;
    if (n >= N_) return;
    float v[H_];
#pragma unroll
    for (int j = 0; j < H_; j++) v[j] = ve[n*H_+j];
#pragma unroll
    for (int h = 0; h < H_; h++) {
        float q = bq[h], k = bk[h];
#pragma unroll
        for (int j = 0; j < H_; j++) { q += v[j]*Wq[j*H_+h]; k += v[j]*Wk[j*H_+h]; }
        g_Q[n*H_+h] = q; g_K[n*H_+h] = k;
    }
}

// ---------------- 2. top-8 + softmax weights ----------------
__global__ void topk_kernel() {
    int n = blockIdx.x, tid = threadIdx.x;   // 128 threads
    __shared__ float sim[N_];
    __shared__ float q[H_];
    __shared__ float rv[128];
    __shared__ int   ri[128];
    __shared__ float tv[TOPK_];
    __shared__ int   tix[TOPK_];
    if (tid < H_) q[tid] = g_Q[n*H_+tid];
    __syncthreads();
    for (int m = tid; m < N_; m += 128) {
        float s = 0.f;
#pragma unroll
        for (int j = 0; j < H_; j++) s += q[j]*g_K[m*H_+j];
        sim[m] = (m == n) ? -1e9f : s;
    }
    __syncthreads();
    for (int t = 0; t < TOPK_; t++) {
        float bv = -1e30f; int bi = 0x7fffffff;
        for (int m = tid; m < N_; m += 128) {
            float s = sim[m];
            if (s > bv) { bv = s; bi = m; }
        }
        rv[tid] = bv; ri[tid] = bi;
        __syncthreads();
        for (int off = 64; off > 0; off >>= 1) {
            if (tid < off) {
                float ov = rv[tid+off]; int oi = ri[tid+off];
                if (ov > rv[tid] || (ov == rv[tid] && oi < ri[tid])) { rv[tid] = ov; ri[tid] = oi; }
            }
            __syncthreads();
        }
        if (tid == 0) { tv[t] = rv[0]; tix[t] = ri[0]; sim[ri[0]] = -1e30f; }
        __syncthreads();
    }
    if (tid == 0) {
        float mx = tv[0], e[TOPK_], s = 0.f;
#pragma unroll
        for (int t = 0; t < TOPK_; t++) { e[t] = expf(tv[t]-mx); s += e[t]; }
        float inv = 1.f/s;
#pragma unroll
        for (int t = 0; t < TOPK_; t++) { g_w[n*TOPK_+t] = e[t]*inv; g_idx[n*TOPK_+t] = tix[t]; }
    }
}

// ---------------- 3. score logits ----------------
__global__ void score_kernel(const float* __restrict__ x,
                             const float* __restrict__ Wscore,
                             const float* __restrict__ bscore) {
    int b = blockIdx.y, l0 = blockIdx.x * 90;
    int w = threadIdx.x >> 5, lane = threadIdx.x & 31;
    for (int l = l0 + w; l < l0 + 90; l += 8) {
        const float4* xr = (const float4*)(x + ((size_t)b*L_+l)*N_);
        const float4* wr = (const float4*)Wscore;
        float s = 0.f;
#pragma unroll
        for (int c = 0; c < 4; c++) {
            float4 v = xr[lane + c*32], ww = wr[lane + c*32];
            s += v.x*ww.x + v.y*ww.y + v.z*ww.z + v.w*ww.w;
        }
#pragma unroll
        for (int o = 16; o > 0; o >>= 1) s += __shfl_xor_sync(0xffffffffu, s, o);
        if (lane == 0) g_logit[b*L_+l] = s + bscore[0];
    }
}

// ---------------- 4. ring gather (launch #3 -> profiled) ----------------
#define TL 8
__global__ void ring_kernel(const float* __restrict__ x) {
    int b = blockIdx.y, l0 = blockIdx.x * TL, tid = threadIdx.x;   // 256 threads
    __shared__ float xt[TL][N_];
    const float* xb = x + (size_t)b*L_*N_ + (size_t)l0*N_;
    for (int i = tid; i < TL*N_/4; i += 256)
        ((float4*)xt)[i] = ((const float4*)xb)[i];
    __syncthreads();
    float* outb = g_ring + (size_t)b*L_*N_ + (size_t)l0*N_;
    for (int o = tid; o < TL*N_; o += 256) {
        int l = o >> 9, n = o & 511;
        float acc = 0.f;
#pragma unroll
        for (int k = 0; k < TOPK_; k++) {
            int id  = __ldg(&g_idx[n*TOPK_+k]);
            float w = __ldg(&g_w[n*TOPK_+k]);
            acc += xt[l][id] * w;
        }
        outb[o] = acc;
    }
}

// ---------------- 5. fused softmax-over-L + weighted sum ----------------
__global__ void csum_kernel(const float* __restrict__ x) {
    int b = blockIdx.y, c = blockIdx.x*128 + threadIdx.x;
    int tid = threadIdx.x;   // 128 threads
    __shared__ float p[L_];
    __shared__ float red[128];
    for (int l = tid; l < L_; l += 128) p[l] = g_logit[b*L_+l];
    __syncthreads();
    float m = -1e30f;
    for (int l = tid; l < L_; l += 128) m = fmaxf(m, p[l]);
    red[tid] = m; __syncthreads();
    for (int o = 64; o > 0; o >>= 1) { if (tid < o) red[tid] = fmaxf(red[tid], red[tid+o]); __syncthreads(); }
    m = red[0]; __syncthreads();
    float s = 0.f;
    for (int l = tid; l < L_; l += 128) { float e = expf(p[l]-m); p[l] = e; s += e; }
    red[tid] = s; __syncthreads();
    for (int o = 64; o > 0; o >>= 1) { if (tid < o) red[tid] += red[tid+o]; __syncthreads(); }
    float inv = 1.f/red[0];
    __syncthreads();
    for (int l = tid; l < L_; l += 128) p[l] *= inv;
    __syncthreads();
    float acc = 0.f;
    const float* xb = x + (size_t)b*L_*N_ + c;
    for (int l = 0; l < L_; l++) acc += p[l]*xb[(size_t)l*N_];
    g_center_raw[b*N_+c] = acc;
}

// ---------------- 6a. center MLP ----------------
__global__ void mlp_kernel(const float* __restrict__ Wc1, const float* __restrict__ bc1,
                           const float* __restrict__ Wc2, const float* __restrict__ bc2,
                           const float* __restrict__ Wcn, const float* __restrict__ bcn) {
    int b = blockIdx.x, tid = threadIdx.x;   // 256 threads
    __shared__ float cr[N_];
    __shared__ float c1[D_];
    __shared__ float c2[D_];
    for (int n = tid; n < N_; n += 256) cr[n] = g_center_raw[b*N_+n];
    __syncthreads();
    {
        int d = tid >> 2, part = tid & 3;
        float s = 0.f;
        for (int n = part*128; n < part*128+128; n++) s += cr[n]*Wc1[n*D_+d];
        s += __shfl_xor_sync(0xffffffffu, s, 1);
        s += __shfl_xor_sync(0xffffffffu, s, 2);
        if (part == 0) {
            s += bc1[d];
            c1[d] = 0.5f*s*(1.f + erff(s*0.7071067811865475f));
        }
    }
    __syncthreads();
    if (tid < D_) {
        float s = bc2[tid];
#pragma unroll
        for (int e = 0; e < D_; e++) s += c1[e]*Wc2[e*D_+tid];
        c2[tid] = 0.5f*s*(1.f + erff(s*0.7071067811865475f));
    }
    __syncthreads();
    for (int n = tid; n < N_; n += 256) {
        float s = bcn[n];
#pragma unroll
        for (int d = 0; d < D_; d++) s += c2[d]*Wcn[d*N_+n];
        g_center[b*N_+n] = s;
    }
}

// ---------------- 6b. cg = center @ Wg[N:2N] ----------------
__global__ void cg_kernel(const float* __restrict__ Wg) {
    int b = blockIdx.x, n2 = blockIdx.y*128 + threadIdx.x;
    __shared__ float ctr[N_];
    for (int n = threadIdx.x; n < N_; n += 128) ctr[n] = g_center[b*N_+n];
    __syncthreads();
    float s = 0.f;
    for (int n = 0; n < N_; n++) s += ctr[n]*Wg[(size_t)(N_+n)*N_ + n2];
    g_cg[b*N_+n2] = s;
}

// ---------------- 7. WMMA bf16-split GEMM (R6 exact: serial, BK=32) -----------------
// C = A @ W   (A: M x 512 fp32 row-major; W: 512 x 512 fp32 row-major used directly)
// mode 0: A=g_ring,  W=Wg(top rows);  epi: sigmoid gate mix -> g_fused (fp32)
// mode 1: A=g_fused, W=Wf;            epi: raw product -> g_h (bias+residual in ln)
#define BM_ 128
#define BN_ 128
#define BK_ 32
#define A_LD 40     // bf16 elems per A smem row
#define W_LD 136    // bf16 elems per W smem row
#define SA_H 0
#define SA_L 10240
#define SW_H 20480
#define SW_L 29184
#define GEMM_SMEM_ 37888
#define STG_LD 68   // fp32 staging row stride (mode-0 epilogue)

__global__ __launch_bounds__(256) void gemm_wmma(int mode,
                                                 const float* __restrict__ Wmat,
                                                 const float* __restrict__ e0) {
    extern __shared__ __align__(128) char smem[];
    const int tid = threadIdx.x, wid = tid >> 5, lane = tid & 31;
    const int wm = wid >> 1, wn = wid & 1;   // warp grid 4(m) x 2(n): warp tile 32 x 64
    const int row0 = blockIdx.x * BM_, col0 = blockIdx.y * BN_;

    const float* A = (mode == 0) ? g_ring : g_fused;

    __nv_bfloat16* sAh = (__nv_bfloat16*)(smem + SA_H);
    __nv_bfloat16* sAl = (__nv_bfloat16*)(smem + SA_L);
    __nv_bfloat16* sWh = (__nv_bfloat16*)(smem + SW_H);
    __nv_bfloat16* sWl = (__nv_bfloat16*)(smem + SW_L);

    wmma::fragment<wmma::accumulator, 16, 16, 16, float> facc[2][4];
#pragma unroll
    for (int mi = 0; mi < 2; mi++)
#pragma unroll
        for (int p = 0; p < 4; p++) wmma::fill_fragment(facc[mi][p], 0.f);

    const int NKB = N_ / BK_;   // 16
    for (int kb = 0; kb < NKB; kb++) {
        const int k0 = kb * BK_;
        __syncthreads();
#pragma unroll
        for (int i = 0; i < 4; i++) {
            int c = i*256 + tid;
            int row = c >> 3, col4 = (c & 7) * 4;
            float4 v = *(const float4*)(A + (size_t)(row0+row)*N_ + k0 + col4);
            __nv_bfloat16 h0,l0_,h1,l1,h2,l2,h3,l3;
            bsplit(v.x, h0, l0_); bsplit(v.y, h1, l1);
            bsplit(v.z, h2, l2);  bsplit(v.w, h3, l3);
            int o = row*A_LD + col4;
            *(__nv_bfloat162*)(sAh + o)     = __nv_bfloat162(h0, h1);
            *(__nv_bfloat162*)(sAh + o + 2) = __nv_bfloat162(h2, h3);
            *(__nv_bfloat162*)(sAl + o)     = __nv_bfloat162(l0_, l1);
            *(__nv_bfloat162*)(sAl + o + 2) = __nv_bfloat162(l2, l3);
        }
#pragma unroll
        for (int i = 0; i < 4; i++) {
            int c = i*256 + tid;
            int row = c >> 5, col4 = (c & 31) * 4;
            float4 v = *(const float4*)(Wmat + (size_t)(k0+row)*N_ + col0 + col4);
            __nv_bfloat16 h0,l0_,h1,l1,h2,l2,h3,l3;
            bsplit(v.x, h0, l0_); bsplit(v.y, h1, l1);
            bsplit(v.z, h2, l2);  bsplit(v.w, h3, l3);
            int o = row*W_LD + col4;
            *(__nv_bfloat162*)(sWh + o)     = __nv_bfloat162(h0, h1);
            *(__nv_bfloat162*)(sWh + o + 2) = __nv_bfloat162(h2, h3);
            *(__nv_bfloat162*)(sWl + o)     = __nv_bfloat162(l0_, l1);
            *(__nv_bfloat162*)(sWl + o + 2) = __nv_bfloat162(l2, l3);
        }
        __syncthreads();

#pragma unroll
        for (int ks = 0; ks < 2; ks++) {
            wmma::fragment<wmma::matrix_a, 16, 16, 16, __nv_bfloat16, wmma::row_major> fah[2], fal[2];
#pragma unroll
            for (int mi = 0; mi < 2; mi++) {
                int aro = (wm*32 + mi*16) * A_LD + ks*16;
                wmma::load_matrix_sync(fah[mi], sAh + aro, A_LD);
                wmma::load_matrix_sync(fal[mi], sAl + aro, A_LD);
            }
#pragma unroll
            for (int p = 0; p < 4; p++) {
                wmma::fragment<wmma::matrix_b, 16, 16, 16, __nv_bfloat16, wmma::row_major> fbh, fbl;
                int bro = (ks*16) * W_LD + wn*64 + p*16;
                wmma::load_matrix_sync(fbh, sWh + bro, W_LD);
                wmma::load_matrix_sync(fbl, sWl + bro, W_LD);
#pragma unroll
                for (int mi = 0; mi < 2; mi++) {
                    wmma::mma_sync(facc[mi][p], fah[mi], fbh, facc[mi][p]);
                    wmma::mma_sync(facc[mi][p], fah[mi], fbl, facc[mi][p]);
                    wmma::mma_sync(facc[mi][p], fal[mi], fbh, facc[mi][p]);
                }
            }
        }
    }
    __syncthreads();

    if (mode == 1) {
#pragma unroll
        for (int mi = 0; mi < 2; mi++)
#pragma unroll
            for (int p = 0; p < 4; p++) {
                float* dst = g_h + (size_t)(row0 + wm*32 + mi*16)*N_ + col0 + wn*64 + p*16;
                wmma::store_matrix_sync(dst, facc[mi][p], N_, wmma::mem_row_major);
            }
        return;
    }

    float* wst = (float*)smem + wid * (16 * STG_LD);
#pragma unroll
    for (int mi = 0; mi < 2; mi++) {
#pragma unroll
        for (int p = 0; p < 4; p++)
            wmma::store_matrix_sync(wst + p*16, facc[mi][p], STG_LD, wmma::mem_row_major);
        __syncwarp();
        int r16 = lane >> 1;
        int coff = (lane & 1) * 32;
        int r = row0 + wm*32 + mi*16 + r16;
        int bb = r / L_;
        size_t rb = (size_t)r * N_;
        const float* myrow = wst + r16*STG_LD + coff;
#pragma unroll
        for (int q = 0; q < 8; q++) {
            float4 v = *(const float4*)(myrow + q*4);
            int c = col0 + wn*64 + coff + q*4;
            float4 o;
#pragma unroll
            for (int t = 0; t < 4; t++) {
                int cc = c + t;
                float vv = (&v.x)[t];
                float pre = vv + g_cg[bb*N_+cc] + e0[cc];
                float g = 1.f/(1.f + expf(-pre));
                float rv = g_ring[rb+cc];
                (&o.x)[t] = g*rv + (1.f-g)*g_center[bb*N_+cc];
            }
            *(float4*)(g_fused + rb + c) = o;
        }
        __syncwarp();
    }
}

// ---------------- 8. LayerNorm over N (+ folded Wf bias and residual) ----------------
__global__ void ln_kernel(const float* __restrict__ gamma, const float* __restrict__ beta,
                          const float* __restrict__ bf, const float* __restrict__ x,
                          float* __restrict__ out) {
    int r = blockIdx.x, tid = threadIdx.x;   // 256 threads
    size_t base = (size_t)r*N_;
    float a  = g_h[base+tid]     + bf[tid]     + x[base+tid];
    float b2 = g_h[base+tid+256] + bf[tid+256] + x[base+tid+256];
    __shared__ float rs[256], rq[256];
    rs[tid] = a + b2;
    rq[tid] = a*a + b2*b2;
    __syncthreads();
    for (int o = 128; o > 0; o >>= 1) {
        if (tid < o) { rs[tid] += rs[tid+o]; rq[tid] += rq[tid+o]; }
        __syncthreads();
    }
    float mu  = rs[0] * (1.f/N_);
    float var = rq[0] * (1.f/N_) - mu*mu;
    float inv = rsqrtf(var + 1e-5f);
    out[base+tid]     = (a  - mu)*inv*gamma[tid]     + beta[tid];
    out[base+tid+256] = (b2 - mu)*inv*gamma[tid+256] + beta[tid+256];
}

// ---------------- launch ----------------
extern "C" void kernel_launch(void* const* d_in, const int* in_sizes, int n_in,
                              void* d_out, int out_size) {
    const float* x      = (const float*)d_in[0];
    const float* ve     = (const float*)d_in[1];
    const float* Wq     = (const float*)d_in[2];
    const float* bq     = (const float*)d_in[3];
    const float* Wk     = (const float*)d_in[4];
    const float* bk     = (const float*)d_in[5];
    const float* Wscore = (const float*)d_in[6];
    const float* bscore = (const float*)d_in[7];
    const float* Wc1    = (const float*)d_in[8];
    const float* bc1    = (const float*)d_in[9];
    const float* Wc2    = (const float*)d_in[10];
    const float* bc2    = (const float*)d_in[11];
    const float* Wcn    = (const float*)d_in[12];
    const float* bcn    = (const float*)d_in[13];
    const float* Wg     = (const float*)d_in[14];
    const float* bg     = (const float*)d_in[15];
    const float* Wf     = (const float*)d_in[16];
    const float* bf     = (const float*)d_in[17];
    const float* gamma  = (const float*)d_in[18];
    const float* beta   = (const float*)d_in[19];
    float* out = (float*)d_out;

    cudaFuncSetAttribute(gemm_wmma, cudaFuncAttributeMaxDynamicSharedMemorySize, GEMM_SMEM_);

    qk_kernel<<<2, 256>>>(ve, Wq, bq, Wk, bk);                            // #0
    topk_kernel<<<512, 128>>>();                                          // #1
    score_kernel<<<dim3(8, B_), 256>>>(x, Wscore, bscore);                // #2
    ring_kernel<<<dim3(L_/TL, B_), 256>>>(x);                             // #3 <- profiled
    csum_kernel<<<dim3(4, B_), 128>>>(x);                                 // #4
    mlp_kernel<<<B_, 256>>>(Wc1, bc1, Wc2, bc2, Wcn, bcn);                // #5
    cg_kernel<<<dim3(B_, 4), 128>>>(Wg);                                  // #6
    gemm_wmma<<<dim3(M_/BM_, N_/BN_), 256, GEMM_SMEM_>>>(0, Wg, bg);      // #7
    gemm_wmma<<<dim3(M_/BM_, N_/BN_), 256, GEMM_SMEM_>>>(1, Wf, nullptr); // #8
    ln_kernel<<<M_, 256>>>(gamma, beta, bf, x, out);                      // #9
}

// round 13
// speedup vs baseline: 1.3288x; 1.1903x over previous
#include <cuda_runtime.h>
#include <cuda_bf16.h>
#include <mma.h>
#include <math.h>
#include <stdint.h>

using namespace nvcuda;

#define B_ 32
#define L_ 720
#define N_ 512
#define H_ 16
#define D_ 64
#define TOPK_ 8
#define M_ (B_*L_)   // 23040

// ---------------- scratch (static device memory; no allocations) ----------------
__device__ float g_Q[N_*H_];
__device__ float g_K[N_*H_];
__device__ int   g_idx[N_*TOPK_];
__device__ float g_w[N_*TOPK_];
__device__ float g_logit[B_*L_];
__device__ float g_center_raw[B_*N_];
__device__ float g_center[B_*N_];
__device__ float g_cg[B_*N_];
__device__ float g_ring[(size_t)M_*N_];
__device__ float g_fused[(size_t)M_*N_];
__device__ float g_h[(size_t)M_*N_];

// ---------------- helpers ----------------
__device__ __forceinline__ void bsplit(float v, __nv_bfloat16& h, __nv_bfloat16& l) {
    h = __float2bfloat16(v);
    l = __float2bfloat16(v - __bfloat162float(h));
}

// ---------------- 1. Q/K projection ----------------
__global__ void qk_kernel(const float* __restrict__ ve,
                          const float* __restrict__ Wq, const float* __restrict__ bq,
                          const float* __restrict__ Wk, const float* __restrict__ bk) {
    int n = blockIdx.x * blockDim.x + threadIdx.x;
    if (n >= N_) return;
    float v[H_];
#pragma unroll
    for (int j = 0; j < H_; j++) v[j] = ve[n*H_+j];
#pragma unroll
    for (int h = 0; h < H_; h++) {
        float q = bq[h], k = bk[h];
#pragma unroll
        for (int j = 0; j < H_; j++) { q += v[j]*Wq[j*H_+h]; k += v[j]*Wk[j*H_+h]; }
        g_Q[n*H_+h] = q; g_K[n*H_+h] = k;
    }
}

// ---------------- 2. top-8 + softmax weights ----------------
__global__ void topk_kernel() {
    int n = blockIdx.x, tid = threadIdx.x;   // 128 threads
    __shared__ float sim[N_];
    __shared__ float q[H_];
    __shared__ float rv[128];
    __shared__ int   ri[128];
    __shared__ float tv[TOPK_];
    __shared__ int   tix[TOPK_];
    if (tid < H_) q[tid] = g_Q[n*H_+tid];
    __syncthreads();
    for (int m = tid; m < N_; m += 128) {
        float s = 0.f;
#pragma unroll
        for (int j = 0; j < H_; j++) s += q[j]*g_K[m*H_+j];
        sim[m] = (m == n) ? -1e9f : s;
    }
    __syncthreads();
    for (int t = 0; t < TOPK_; t++) {
        float bv = -1e30f; int bi = 0x7fffffff;
        for (int m = tid; m < N_; m += 128) {
            float s = sim[m];
            if (s > bv) { bv = s; bi = m; }
        }
        rv[tid] = bv; ri[tid] = bi;
        __syncthreads();
        for (int off = 64; off > 0; off >>= 1) {
            if (tid < off) {
                float ov = rv[tid+off]; int oi = ri[tid+off];
                if (ov > rv[tid] || (ov == rv[tid] && oi < ri[tid])) { rv[tid] = ov; ri[tid] = oi; }
            }
            __syncthreads();
        }
        if (tid == 0) { tv[t] = rv[0]; tix[t] = ri[0]; sim[ri[0]] = -1e30f; }
        __syncthreads();
    }
    if (tid == 0) {
        float mx = tv[0], e[TOPK_], s = 0.f;
#pragma unroll
        for (int t = 0; t < TOPK_; t++) { e[t] = expf(tv[t]-mx); s += e[t]; }
        float inv = 1.f/s;
#pragma unroll
        for (int t = 0; t < TOPK_; t++) { g_w[n*TOPK_+t] = e[t]*inv; g_idx[n*TOPK_+t] = tix[t]; }
    }
}

// ---------------- 3. score logits ----------------
__global__ void score_kernel(const float* __restrict__ x,
                             const float* __restrict__ Wscore,
                             const float* __restrict__ bscore) {
    int b = blockIdx.y, l0 = blockIdx.x * 90;
    int w = threadIdx.x >> 5, lane = threadIdx.x & 31;
    for (int l = l0 + w; l < l0 + 90; l += 8) {
        const float4* xr = (const float4*)(x + ((size_t)b*L_+l)*N_);
        const float4* wr = (const float4*)Wscore;
        float s = 0.f;
#pragma unroll
        for (int c = 0; c < 4; c++) {
            float4 v = xr[lane + c*32], ww = wr[lane + c*32];
            s += v.x*ww.x + v.y*ww.y + v.z*ww.z + v.w*ww.w;
        }
#pragma unroll
        for (int o = 16; o > 0; o >>= 1) s += __shfl_xor_sync(0xffffffffu, s, o);
        if (lane == 0) g_logit[b*L_+l] = s + bscore[0];
    }
}

// ---------------- 4. ring gather, conflict-free padded-transpose version -------------
// out[r][n] = sum_k x[r][idx[n,k]] * w[n,k], rows flattened over (b,l).
// 32 rows per block in xt[32][513]; lane=row, warp covers 64 n's.
// bank(xt[lane][id]) = (lane*513 + id) % 32 = (lane + id) % 32 -> conflict-free.
#define RL 32
#define RP 513
#define RING_SMEM_ ((2*RL*RP)*4 + N_*TOPK_*8)   // xt + ot + packed pairs = 164 KB

__global__ __launch_bounds__(256) void ring_kernel(const float* __restrict__ x) {
    extern __shared__ float sm[];
    float* xt = sm;                       // [RL][RP]
    float* ot = sm + RL*RP;               // [RL][RP]
    int2*  pr = (int2*)(sm + 2*RL*RP);    // [N_*TOPK_] packed (idx, w)
    const int tid = threadIdx.x;
    const size_t r0 = (size_t)blockIdx.x * RL;

    // load 32 rows of x into padded tile (coalesced LDG, conflict-free STS)
    for (int e = tid; e < RL*N_; e += 256) {
        int i = e >> 9, c = e & 511;
        xt[i*RP + c] = x[(r0+i)*N_ + c];
    }
    // pack (idx, w) pairs
    for (int e = tid; e < N_*TOPK_; e += 256)
        pr[e] = make_int2(g_idx[e], __float_as_int(g_w[e]));
    __syncthreads();

    const int wid = tid >> 5, lane = tid & 31;
    const float* xrow = xt + lane*RP;
#pragma unroll 4
    for (int n = wid*64; n < wid*64 + 64; n++) {
        float acc = 0.f;
#pragma unroll
        for (int k = 0; k < TOPK_; k++) {
            int2 p = pr[n*TOPK_ + k];          // LDS.64 broadcast (same addr warp-wide)
            acc += __int_as_float(p.y) * xrow[p.x];   // conflict-free LDS
        }
        ot[lane*RP + n] = acc;                 // bank (lane+n)%32 -> conflict-free
    }
    __syncthreads();

    // coalesced write-out
    for (int e = tid; e < RL*N_; e += 256) {
        int i = e >> 9, c = e & 511;
        g_ring[(r0+i)*N_ + c] = ot[i*RP + c];
    }
}

// ---------------- 5. fused softmax-over-L + weighted sum ----------------
__global__ void csum_kernel(const float* __restrict__ x) {
    int b = blockIdx.y, c = blockIdx.x*128 + threadIdx.x;
    int tid = threadIdx.x;   // 128 threads
    __shared__ float p[L_];
    __shared__ float red[128];
    for (int l = tid; l < L_; l += 128) p[l] = g_logit[b*L_+l];
    __syncthreads();
    float m = -1e30f;
    for (int l = tid; l < L_; l += 128) m = fmaxf(m, p[l]);
    red[tid] = m; __syncthreads();
    for (int o = 64; o > 0; o >>= 1) { if (tid < o) red[tid] = fmaxf(red[tid], red[tid+o]); __syncthreads(); }
    m = red[0]; __syncthreads();
    float s = 0.f;
    for (int l = tid; l < L_; l += 128) { float e = expf(p[l]-m); p[l] = e; s += e; }
    red[tid] = s; __syncthreads();
    for (int o = 64; o > 0; o >>= 1) { if (tid < o) red[tid] += red[tid+o]; __syncthreads(); }
    float inv = 1.f/red[0];
    __syncthreads();
    for (int l = tid; l < L_; l += 128) p[l] *= inv;
    __syncthreads();
    float acc = 0.f;
    const float* xb = x + (size_t)b*L_*N_ + c;
    for (int l = 0; l < L_; l++) acc += p[l]*xb[(size_t)l*N_];
    g_center_raw[b*N_+c] = acc;
}

// ---------------- 6a. center MLP ----------------
__global__ void mlp_kernel(const float* __restrict__ Wc1, const float* __restrict__ bc1,
                           const float* __restrict__ Wc2, const float* __restrict__ bc2,
                           const float* __restrict__ Wcn, const float* __restrict__ bcn) {
    int b = blockIdx.x, tid = threadIdx.x;   // 256 threads
    __shared__ float cr[N_];
    __shared__ float c1[D_];
    __shared__ float c2[D_];
    for (int n = tid; n < N_; n += 256) cr[n] = g_center_raw[b*N_+n];
    __syncthreads();
    {
        int d = tid >> 2, part = tid & 3;
        float s = 0.f;
        for (int n = part*128; n < part*128+128; n++) s += cr[n]*Wc1[n*D_+d];
        s += __shfl_xor_sync(0xffffffffu, s, 1);
        s += __shfl_xor_sync(0xffffffffu, s, 2);
        if (part == 0) {
            s += bc1[d];
            c1[d] = 0.5f*s*(1.f + erff(s*0.7071067811865475f));
        }
    }
    __syncthreads();
    if (tid < D_) {
        float s = bc2[tid];
#pragma unroll
        for (int e = 0; e < D_; e++) s += c1[e]*Wc2[e*D_+tid];
        c2[tid] = 0.5f*s*(1.f + erff(s*0.7071067811865475f));
    }
    __syncthreads();
    for (int n = tid; n < N_; n += 256) {
        float s = bcn[n];
#pragma unroll
        for (int d = 0; d < D_; d++) s += c2[d]*Wcn[d*N_+n];
        g_center[b*N_+n] = s;
    }
}

// ---------------- 6b. cg = center @ Wg[N:2N] ----------------
__global__ void cg_kernel(const float* __restrict__ Wg) {
    int b = blockIdx.x, n2 = blockIdx.y*128 + threadIdx.x;
    __shared__ float ctr[N_];
    for (int n = threadIdx.x; n < N_; n += 128) ctr[n] = g_center[b*N_+n];
    __syncthreads();
    float s = 0.f;
    for (int n = 0; n < N_; n++) s += ctr[n]*Wg[(size_t)(N_+n)*N_ + n2];
    g_cg[b*N_+n2] = s;
}

// ---------------- 7. WMMA bf16-split GEMM (champion version: serial, BK=32) ----------
#define BM_ 128
#define BN_ 128
#define BK_ 32
#define A_LD 40
#define W_LD 136
#define SA_H 0
#define SA_L 10240
#define SW_H 20480
#define SW_L 29184
#define GEMM_SMEM_ 37888
#define STG_LD 68

__global__ __launch_bounds__(256) void gemm_wmma(int mode,
                                                 const float* __restrict__ Wmat,
                                                 const float* __restrict__ e0) {
    extern __shared__ __align__(128) char smem[];
    const int tid = threadIdx.x, wid = tid >> 5, lane = tid & 31;
    const int wm = wid >> 1, wn = wid & 1;
    const int row0 = blockIdx.x * BM_, col0 = blockIdx.y * BN_;

    const float* A = (mode == 0) ? g_ring : g_fused;

    __nv_bfloat16* sAh = (__nv_bfloat16*)(smem + SA_H);
    __nv_bfloat16* sAl = (__nv_bfloat16*)(smem + SA_L);
    __nv_bfloat16* sWh = (__nv_bfloat16*)(smem + SW_H);
    __nv_bfloat16* sWl = (__nv_bfloat16*)(smem + SW_L);

    wmma::fragment<wmma::accumulator, 16, 16, 16, float> facc[2][4];
#pragma unroll
    for (int mi = 0; mi < 2; mi++)
#pragma unroll
        for (int p = 0; p < 4; p++) wmma::fill_fragment(facc[mi][p], 0.f);

    const int NKB = N_ / BK_;   // 16
    for (int kb = 0; kb < NKB; kb++) {
        const int k0 = kb * BK_;
        __syncthreads();
#pragma unroll
        for (int i = 0; i < 4; i++) {
            int c = i*256 + tid;
            int row = c >> 3, col4 = (c & 7) * 4;
            float4 v = *(const float4*)(A + (size_t)(row0+row)*N_ + k0 + col4);
            __nv_bfloat16 h0,l0_,h1,l1,h2,l2,h3,l3;
            bsplit(v.x, h0, l0_); bsplit(v.y, h1, l1);
            bsplit(v.z, h2, l2);  bsplit(v.w, h3, l3);
            int o = row*A_LD + col4;
            *(__nv_bfloat162*)(sAh + o)     = __nv_bfloat162(h0, h1);
            *(__nv_bfloat162*)(sAh + o + 2) = __nv_bfloat162(h2, h3);
            *(__nv_bfloat162*)(sAl + o)     = __nv_bfloat162(l0_, l1);
            *(__nv_bfloat162*)(sAl + o + 2) = __nv_bfloat162(l2, l3);
        }
#pragma unroll
        for (int i = 0; i < 4; i++) {
            int c = i*256 + tid;
            int row = c >> 5, col4 = (c & 31) * 4;
            float4 v = *(const float4*)(Wmat + (size_t)(k0+row)*N_ + col0 + col4);
            __nv_bfloat16 h0,l0_,h1,l1,h2,l2,h3,l3;
            bsplit(v.x, h0, l0_); bsplit(v.y, h1, l1);
            bsplit(v.z, h2, l2);  bsplit(v.w, h3, l3);
            int o = row*W_LD + col4;
            *(__nv_bfloat162*)(sWh + o)     = __nv_bfloat162(h0, h1);
            *(__nv_bfloat162*)(sWh + o + 2) = __nv_bfloat162(h2, h3);
            *(__nv_bfloat162*)(sWl + o)     = __nv_bfloat162(l0_, l1);
            *(__nv_bfloat162*)(sWl + o + 2) = __nv_bfloat162(l2, l3);
        }
        __syncthreads();

#pragma unroll
        for (int ks = 0; ks < 2; ks++) {
            wmma::fragment<wmma::matrix_a, 16, 16, 16, __nv_bfloat16, wmma::row_major> fah[2], fal[2];
#pragma unroll
            for (int mi = 0; mi < 2; mi++) {
                int aro = (wm*32 + mi*16) * A_LD + ks*16;
                wmma::load_matrix_sync(fah[mi], sAh + aro, A_LD);
                wmma::load_matrix_sync(fal[mi], sAl + aro, A_LD);
            }
#pragma unroll
            for (int p = 0; p < 4; p++) {
                wmma::fragment<wmma::matrix_b, 16, 16, 16, __nv_bfloat16, wmma::row_major> fbh, fbl;
                int bro = (ks*16) * W_LD + wn*64 + p*16;
                wmma::load_matrix_sync(fbh, sWh + bro, W_LD);
                wmma::load_matrix_sync(fbl, sWl + bro, W_LD);
#pragma unroll
                for (int mi = 0; mi < 2; mi++) {
                    wmma::mma_sync(facc[mi][p], fah[mi], fbh, facc[mi][p]);
                    wmma::mma_sync(facc[mi][p], fah[mi], fbl, facc[mi][p]);
                    wmma::mma_sync(facc[mi][p], fal[mi], fbh, facc[mi][p]);
                }
            }
        }
    }
    __syncthreads();

    if (mode == 1) {
#pragma unroll
        for (int mi = 0; mi < 2; mi++)
#pragma unroll
            for (int p = 0; p < 4; p++) {
                float* dst = g_h + (size_t)(row0 + wm*32 + mi*16)*N_ + col0 + wn*64 + p*16;
                wmma::store_matrix_sync(dst, facc[mi][p], N_, wmma::mem_row_major);
            }
        return;
    }

    float* wst = (float*)smem + wid * (16 * STG_LD);
#pragma unroll
    for (int mi = 0; mi < 2; mi++) {
#pragma unroll
        for (int p = 0; p < 4; p++)
            wmma::store_matrix_sync(wst + p*16, facc[mi][p], STG_LD, wmma::mem_row_major);
        __syncwarp();
        int r16 = lane >> 1;
        int coff = (lane & 1) * 32;
        int r = row0 + wm*32 + mi*16 + r16;
        int bb = r / L_;
        size_t rb = (size_t)r * N_;
        const float* myrow = wst + r16*STG_LD + coff;
#pragma unroll
        for (int q = 0; q < 8; q++) {
            float4 v = *(const float4*)(myrow + q*4);
            int c = col0 + wn*64 + coff + q*4;
            float4 o;
#pragma unroll
            for (int t = 0; t < 4; t++) {
                int cc = c + t;
                float vv = (&v.x)[t];
                float pre = vv + g_cg[bb*N_+cc] + e0[cc];
                float g = 1.f/(1.f + expf(-pre));
                float rv = g_ring[rb+cc];
                (&o.x)[t] = g*rv + (1.f-g)*g_center[bb*N_+cc];
            }
            *(float4*)(g_fused + rb + c) = o;
        }
        __syncwarp();
    }
}

// ---------------- 8. LayerNorm over N (+ folded Wf bias and residual) ----------------
__global__ void ln_kernel(const float* __restrict__ gamma, const float* __restrict__ beta,
                          const float* __restrict__ bf, const float* __restrict__ x,
                          float* __restrict__ out) {
    int r = blockIdx.x, tid = threadIdx.x;   // 256 threads
    size_t base = (size_t)r*N_;
    float a  = g_h[base+tid]     + bf[tid]     + x[base+tid];
    float b2 = g_h[base+tid+256] + bf[tid+256] + x[base+tid+256];
    __shared__ float rs[256], rq[256];
    rs[tid] = a + b2;
    rq[tid] = a*a + b2*b2;
    __syncthreads();
    for (int o = 128; o > 0; o >>= 1) {
        if (tid < o) { rs[tid] += rs[tid+o]; rq[tid] += rq[tid+o]; }
        __syncthreads();
    }
    float mu  = rs[0] * (1.f/N_);
    float var = rq[0] * (1.f/N_) - mu*mu;
    float inv = rsqrtf(var + 1e-5f);
    out[base+tid]     = (a  - mu)*inv*gamma[tid]     + beta[tid];
    out[base+tid+256] = (b2 - mu)*inv*gamma[tid+256] + beta[tid+256];
}

// ---------------- launch ----------------
extern "C" void kernel_launch(void* const* d_in, const int* in_sizes, int n_in,
                              void* d_out, int out_size) {
    const float* x      = (const float*)d_in[0];
    const float* ve     = (const float*)d_in[1];
    const float* Wq     = (const float*)d_in[2];
    const float* bq     = (const float*)d_in[3];
    const float* Wk     = (const float*)d_in[4];
    const float* bk     = (const float*)d_in[5];
    const float* Wscore = (const float*)d_in[6];
    const float* bscore = (const float*)d_in[7];
    const float* Wc1    = (const float*)d_in[8];
    const float* bc1    = (const float*)d_in[9];
    const float* Wc2    = (const float*)d_in[10];
    const float* bc2    = (const float*)d_in[11];
    const float* Wcn    = (const float*)d_in[12];
    const float* bcn    = (const float*)d_in[13];
    const float* Wg     = (const float*)d_in[14];
    const float* bg     = (const float*)d_in[15];
    const float* Wf     = (const float*)d_in[16];
    const float* bf     = (const float*)d_in[17];
    const float* gamma  = (const float*)d_in[18];
    const float* beta   = (const float*)d_in[19];
    float* out = (float*)d_out;

    cudaFuncSetAttribute(gemm_wmma, cudaFuncAttributeMaxDynamicSharedMemorySize, GEMM_SMEM_);
    cudaFuncSetAttribute(ring_kernel, cudaFuncAttributeMaxDynamicSharedMemorySize, RING_SMEM_);

    qk_kernel<<<2, 256>>>(ve, Wq, bq, Wk, bk);                            // #0
    topk_kernel<<<512, 128>>>();                                          // #1
    score_kernel<<<dim3(8, B_), 256>>>(x, Wscore, bscore);                // #2
    ring_kernel<<<M_/RL, 256, RING_SMEM_>>>(x);                           // #3 <- profiled
    csum_kernel<<<dim3(4, B_), 128>>>(x);                                 // #4
    mlp_kernel<<<B_, 256>>>(Wc1, bc1, Wc2, bc2, Wcn, bcn);                // #5
    cg_kernel<<<dim3(B_, 4), 128>>>(Wg);                                  // #6
    gemm_wmma<<<dim3(M_/BM_, N_/BN_), 256, GEMM_SMEM_>>>(0, Wg, bg);      // #7
    gemm_wmma<<<dim3(M_/BM_, N_/BN_), 256, GEMM_SMEM_>>>(1, Wf, nullptr); // #8
    ln_kernel<<<M_, 256>>>(gamma, beta, bf, x, out);                      // #9
}

// round 14
// speedup vs baseline: 1.3874x; 1.0441x over previous
#include <cuda_runtime.h>
#include <cuda_bf16.h>
#include <mma.h>
#include <math.h>
#include <stdint.h>

using namespace nvcuda;

#define B_ 32
#define L_ 720
#define N_ 512
#define H_ 16
#define D_ 64
#define TOPK_ 8
#define M_ (B_*L_)   // 23040

// ---------------- scratch (static device memory; no allocations) ----------------
__device__ float g_Q[N_*H_];
__device__ float g_K[N_*H_];
__device__ int   g_idx[N_*TOPK_];
__device__ float g_w[N_*TOPK_];
__device__ float g_logit[B_*L_];
__device__ float g_center_raw[B_*N_];
__device__ float g_center[B_*N_];
__device__ float g_cg[B_*N_];
__device__ float g_ring[(size_t)M_*N_];
__device__ float g_fused[(size_t)M_*N_];
__device__ float g_h[(size_t)M_*N_];
__device__ __align__(16) __nv_bfloat16 g_Wgh[N_*N_];   // hi/lo split of Wg top half (no transpose)
__device__ __align__(16) __nv_bfloat16 g_Wgl[N_*N_];
__device__ __align__(16) __nv_bfloat16 g_Wfh[N_*N_];
__device__ __align__(16) __nv_bfloat16 g_Wfl[N_*N_];

// ---------------- helpers ----------------
__device__ __forceinline__ void bsplit(float v, __nv_bfloat16& h, __nv_bfloat16& l) {
    h = __float2bfloat16(v);
    l = __float2bfloat16(v - __bfloat162float(h));
}

// ---------------- 0. elementwise W split (bit-identical to in-kernel split) ----------
__global__ void wsplit_kernel(const float* __restrict__ W, int which) {
    int i = blockIdx.x * 256 + threadIdx.x;   // N*N = 262144 elements
    __nv_bfloat16* Th = which ? g_Wfh : g_Wgh;
    __nv_bfloat16* Tl = which ? g_Wfl : g_Wgl;
    __nv_bfloat16 h, l;
    bsplit(W[i], h, l);
    Th[i] = h; Tl[i] = l;
}

// ---------------- 1. Q/K projection ----------------
__global__ void qk_kernel(const float* __restrict__ ve,
                          const float* __restrict__ Wq, const float* __restrict__ bq,
                          const float* __restrict__ Wk, const float* __restrict__ bk) {
    int n = blockIdx.x * blockDim.x + threadIdx.x;
    if (n >= N_) return;
    float v[H_];
#pragma unroll
    for (int j = 0; j < H_; j++) v[j] = ve[n*H_+j];
#pragma unroll
    for (int h = 0; h < H_; h++) {
        float q = bq[h], k = bk[h];
#pragma unroll
        for (int j = 0; j < H_; j++) { q += v[j]*Wq[j*H_+h]; k += v[j]*Wk[j*H_+h]; }
        g_Q[n*H_+h] = q; g_K[n*H_+h] = k;
    }
}

// ---------------- 2. top-8 + softmax weights ----------------
__global__ void topk_kernel() {
    int n = blockIdx.x, tid = threadIdx.x;   // 128 threads
    __shared__ float sim[N_];
    __shared__ float q[H_];
    __shared__ float rv[128];
    __shared__ int   ri[128];
    __shared__ float tv[TOPK_];
    __shared__ int   tix[TOPK_];
    if (tid < H_) q[tid] = g_Q[n*H_+tid];
    __syncthreads();
    for (int m = tid; m < N_; m += 128) {
        float s = 0.f;
#pragma unroll
        for (int j = 0; j < H_; j++) s += q[j]*g_K[m*H_+j];
        sim[m] = (m == n) ? -1e9f : s;
    }
    __syncthreads();
    for (int t = 0; t < TOPK_; t++) {
        float bv = -1e30f; int bi = 0x7fffffff;
        for (int m = tid; m < N_; m += 128) {
            float s = sim[m];
            if (s > bv) { bv = s; bi = m; }
        }
        rv[tid] = bv; ri[tid] = bi;
        __syncthreads();
        for (int off = 64; off > 0; off >>= 1) {
            if (tid < off) {
                float ov = rv[tid+off]; int oi = ri[tid+off];
                if (ov > rv[tid] || (ov == rv[tid] && oi < ri[tid])) { rv[tid] = ov; ri[tid] = oi; }
            }
            __syncthreads();
        }
        if (tid == 0) { tv[t] = rv[0]; tix[t] = ri[0]; sim[ri[0]] = -1e30f; }
        __syncthreads();
    }
    if (tid == 0) {
        float mx = tv[0], e[TOPK_], s = 0.f;
#pragma unroll
        for (int t = 0; t < TOPK_; t++) { e[t] = expf(tv[t]-mx); s += e[t]; }
        float inv = 1.f/s;
#pragma unroll
        for (int t = 0; t < TOPK_; t++) { g_w[n*TOPK_+t] = e[t]*inv; g_idx[n*TOPK_+t] = tix[t]; }
    }
}

// ---------------- 3. score logits ----------------
__global__ void score_kernel(const float* __restrict__ x,
                             const float* __restrict__ Wscore,
                             const float* __restrict__ bscore) {
    int b = blockIdx.y, l0 = blockIdx.x * 90;
    int w = threadIdx.x >> 5, lane = threadIdx.x & 31;
    for (int l = l0 + w; l < l0 + 90; l += 8) {
        const float4* xr = (const float4*)(x + ((size_t)b*L_+l)*N_);
        const float4* wr = (const float4*)Wscore;
        float s = 0.f;
#pragma unroll
        for (int c = 0; c < 4; c++) {
            float4 v = xr[lane + c*32], ww = wr[lane + c*32];
            s += v.x*ww.x + v.y*ww.y + v.z*ww.z + v.w*ww.w;
        }
#pragma unroll
        for (int o = 16; o > 0; o >>= 1) s += __shfl_xor_sync(0xffffffffu, s, o);
        if (lane == 0) g_logit[b*L_+l] = s + bscore[0];
    }
}

// ---------------- 4. ring gather, conflict-free, 512 threads ----------------
#define RL 32
#define RP 513
#define RING_SMEM_ ((2*RL*RP)*4 + N_*TOPK_*8)   // xt + ot + packed pairs = 164 KB

__global__ __launch_bounds__(512) void ring_kernel(const float* __restrict__ x) {
    extern __shared__ float sm[];
    float* xt = sm;                       // [RL][RP]
    float* ot = sm + RL*RP;               // [RL][RP]
    int2*  pr = (int2*)(sm + 2*RL*RP);    // [N_*TOPK_] packed (idx, w)
    const int tid = threadIdx.x;
    const size_t r0 = (size_t)blockIdx.x * RL;

    for (int e = tid; e < RL*N_; e += 512) {
        int i = e >> 9, c = e & 511;
        xt[i*RP + c] = x[(r0+i)*N_ + c];
    }
    for (int e = tid; e < N_*TOPK_; e += 512)
        pr[e] = make_int2(g_idx[e], __float_as_int(g_w[e]));
    __syncthreads();

    const int wid = tid >> 5, lane = tid & 31;   // 16 warps x 32 cols
    const float* xrow = xt + lane*RP;
#pragma unroll 4
    for (int n = wid*32; n < wid*32 + 32; n++) {
        float acc = 0.f;
#pragma unroll
        for (int k = 0; k < TOPK_; k++) {
            int2 p = pr[n*TOPK_ + k];
            acc += __int_as_float(p.y) * xrow[p.x];
        }
        ot[lane*RP + n] = acc;
    }
    __syncthreads();

    for (int e = tid; e < RL*N_; e += 512) {
        int i = e >> 9, c = e & 511;
        g_ring[(r0+i)*N_ + c] = ot[i*RP + c];
    }
}

// ---------------- 5. fused softmax-over-L + weighted sum ----------------
__global__ void csum_kernel(const float* __restrict__ x) {
    int b = blockIdx.y, c = blockIdx.x*128 + threadIdx.x;
    int tid = threadIdx.x;   // 128 threads
    __shared__ float p[L_];
    __shared__ float red[128];
    for (int l = tid; l < L_; l += 128) p[l] = g_logit[b*L_+l];
    __syncthreads();
    float m = -1e30f;
    for (int l = tid; l < L_; l += 128) m = fmaxf(m, p[l]);
    red[tid] = m; __syncthreads();
    for (int o = 64; o > 0; o >>= 1) { if (tid < o) red[tid] = fmaxf(red[tid], red[tid+o]); __syncthreads(); }
    m = red[0]; __syncthreads();
    float s = 0.f;
    for (int l = tid; l < L_; l += 128) { float e = expf(p[l]-m); p[l] = e; s += e; }
    red[tid] = s; __syncthreads();
    for (int o = 64; o > 0; o >>= 1) { if (tid < o) red[tid] += red[tid+o]; __syncthreads(); }
    float inv = 1.f/red[0];
    __syncthreads();
    for (int l = tid; l < L_; l += 128) p[l] *= inv;
    __syncthreads();
    float acc = 0.f;
    const float* xb = x + (size_t)b*L_*N_ + c;
    for (int l = 0; l < L_; l++) acc += p[l]*xb[(size_t)l*N_];
    g_center_raw[b*N_+c] = acc;
}

// ---------------- 6a. center MLP ----------------
__global__ void mlp_kernel(const float* __restrict__ Wc1, const float* __restrict__ bc1,
                           const float* __restrict__ Wc2, const float* __restrict__ bc2,
                           const float* __restrict__ Wcn, const float* __restrict__ bcn) {
    int b = blockIdx.x, tid = threadIdx.x;   // 256 threads
    __shared__ float cr[N_];
    __shared__ float c1[D_];
    __shared__ float c2[D_];
    for (int n = tid; n < N_; n += 256) cr[n] = g_center_raw[b*N_+n];
    __syncthreads();
    {
        int d = tid >> 2, part = tid & 3;
        float s = 0.f;
        for (int n = part*128; n < part*128+128; n++) s += cr[n]*Wc1[n*D_+d];
        s += __shfl_xor_sync(0xffffffffu, s, 1);
        s += __shfl_xor_sync(0xffffffffu, s, 2);
        if (part == 0) {
            s += bc1[d];
            c1[d] = 0.5f*s*(1.f + erff(s*0.7071067811865475f));
        }
    }
    __syncthreads();
    if (tid < D_) {
        float s = bc2[tid];
#pragma unroll
        for (int e = 0; e < D_; e++) s += c1[e]*Wc2[e*D_+tid];
        c2[tid] = 0.5f*s*(1.f + erff(s*0.7071067811865475f));
    }
    __syncthreads();
    for (int n = tid; n < N_; n += 256) {
        float s = bcn[n];
#pragma unroll
        for (int d = 0; d < D_; d++) s += c2[d]*Wcn[d*N_+n];
        g_center[b*N_+n] = s;
    }
}

// ---------------- 6b. cg = center @ Wg[N:2N] ----------------
__global__ void cg_kernel(const float* __restrict__ Wg) {
    int b = blockIdx.x, n2 = blockIdx.y*128 + threadIdx.x;
    __shared__ float ctr[N_];
    for (int n = threadIdx.x; n < N_; n += 128) ctr[n] = g_center[b*N_+n];
    __syncthreads();
    float s = 0.f;
    for (int n = 0; n < N_; n++) s += ctr[n]*Wg[(size_t)(N_+n)*N_ + n2];
    g_cg[b*N_+n2] = s;
}

// ---------------- 7. WMMA bf16-split GEMM: A split in-kernel, W pre-split ------------
#define BM_ 128
#define BN_ 128
#define BK_ 32
#define A_LD 40
#define W_LD 136
#define SA_H 0
#define SA_L 10240
#define SW_H 20480
#define SW_L 29184
#define GEMM_SMEM_ 37888
#define STG_LD 68

__global__ __launch_bounds__(256) void gemm_wmma(int mode,
                                                 const float* __restrict__ e0) {
    extern __shared__ __align__(128) char smem[];
    const int tid = threadIdx.x, wid = tid >> 5, lane = tid & 31;
    const int wm = wid >> 1, wn = wid & 1;
    const int row0 = blockIdx.x * BM_, col0 = blockIdx.y * BN_;

    const float* A = (mode == 0) ? g_ring : g_fused;
    const __nv_bfloat16* Wh = (mode == 0) ? g_Wgh : g_Wfh;
    const __nv_bfloat16* Wl = (mode == 0) ? g_Wgl : g_Wfl;

    __nv_bfloat16* sAh = (__nv_bfloat16*)(smem + SA_H);
    __nv_bfloat16* sAl = (__nv_bfloat16*)(smem + SA_L);
    __nv_bfloat16* sWh = (__nv_bfloat16*)(smem + SW_H);
    __nv_bfloat16* sWl = (__nv_bfloat16*)(smem + SW_L);

    wmma::fragment<wmma::accumulator, 16, 16, 16, float> facc[2][4];
#pragma unroll
    for (int mi = 0; mi < 2; mi++)
#pragma unroll
        for (int p = 0; p < 4; p++) wmma::fill_fragment(facc[mi][p], 0.f);

    const int NKB = N_ / BK_;   // 16
    for (int kb = 0; kb < NKB; kb++) {
        const int k0 = kb * BK_;
        __syncthreads();
        // A tile: 128 x 32 fp32 -> split. 1024 float4 chunks, 4/thread.
#pragma unroll
        for (int i = 0; i < 4; i++) {
            int c = i*256 + tid;
            int row = c >> 3, col4 = (c & 7) * 4;
            float4 v = *(const float4*)(A + (size_t)(row0+row)*N_ + k0 + col4);
            __nv_bfloat16 h0,l0_,h1,l1,h2,l2,h3,l3;
            bsplit(v.x, h0, l0_); bsplit(v.y, h1, l1);
            bsplit(v.z, h2, l2);  bsplit(v.w, h3, l3);
            int o = row*A_LD + col4;
            *(__nv_bfloat162*)(sAh + o)     = __nv_bfloat162(h0, h1);
            *(__nv_bfloat162*)(sAh + o + 2) = __nv_bfloat162(h2, h3);
            *(__nv_bfloat162*)(sAl + o)     = __nv_bfloat162(l0_, l1);
            *(__nv_bfloat162*)(sAl + o + 2) = __nv_bfloat162(l2, l3);
        }
        // W tile: 32 x 128 bf16 hi + lo, pure copies. 512+512 uint4 chunks, 2+2/thread.
#pragma unroll
        for (int i = 0; i < 2; i++) {
            int c = i*256 + tid;
            int row = c >> 4, c8 = (c & 15) * 8;
            size_t go = (size_t)(k0+row)*N_ + col0 + c8;
            int o = row*W_LD + c8;
            *(uint4*)(sWh + o) = *(const uint4*)(Wh + go);
            *(uint4*)(sWl + o) = *(const uint4*)(Wl + go);
        }
        __syncthreads();

#pragma unroll
        for (int ks = 0; ks < 2; ks++) {
            wmma::fragment<wmma::matrix_a, 16, 16, 16, __nv_bfloat16, wmma::row_major> fah[2], fal[2];
#pragma unroll
            for (int mi = 0; mi < 2; mi++) {
                int aro = (wm*32 + mi*16) * A_LD + ks*16;
                wmma::load_matrix_sync(fah[mi], sAh + aro, A_LD);
                wmma::load_matrix_sync(fal[mi], sAl + aro, A_LD);
            }
#pragma unroll
            for (int p = 0; p < 4; p++) {
                wmma::fragment<wmma::matrix_b, 16, 16, 16, __nv_bfloat16, wmma::row_major> fbh, fbl;
                int bro = (ks*16) * W_LD + wn*64 + p*16;
                wmma::load_matrix_sync(fbh, sWh + bro, W_LD);
                wmma::load_matrix_sync(fbl, sWl + bro, W_LD);
#pragma unroll
                for (int mi = 0; mi < 2; mi++) {
                    wmma::mma_sync(facc[mi][p], fah[mi], fbh, facc[mi][p]);
                    wmma::mma_sync(facc[mi][p], fah[mi], fbl, facc[mi][p]);
                    wmma::mma_sync(facc[mi][p], fal[mi], fbh, facc[mi][p]);
                }
            }
        }
    }
    __syncthreads();

    if (mode == 1) {
#pragma unroll
        for (int mi = 0; mi < 2; mi++)
#pragma unroll
            for (int p = 0; p < 4; p++) {
                float* dst = g_h + (size_t)(row0 + wm*32 + mi*16)*N_ + col0 + wn*64 + p*16;
                wmma::store_matrix_sync(dst, facc[mi][p], N_, wmma::mem_row_major);
            }
        return;
    }

    float* wst = (float*)smem + wid * (16 * STG_LD);
#pragma unroll
    for (int mi = 0; mi < 2; mi++) {
#pragma unroll
        for (int p = 0; p < 4; p++)
            wmma::store_matrix_sync(wst + p*16, facc[mi][p], STG_LD, wmma::mem_row_major);
        __syncwarp();
        int r16 = lane >> 1;
        int coff = (lane & 1) * 32;
        int r = row0 + wm*32 + mi*16 + r16;
        int bb = r / L_;
        size_t rb = (size_t)r * N_;
        const float* myrow = wst + r16*STG_LD + coff;
#pragma unroll
        for (int q = 0; q < 8; q++) {
            float4 v = *(const float4*)(myrow + q*4);
            int c = col0 + wn*64 + coff + q*4;
            float4 o;
#pragma unroll
            for (int t = 0; t < 4; t++) {
                int cc = c + t;
                float vv = (&v.x)[t];
                float pre = vv + g_cg[bb*N_+cc] + e0[cc];
                float g = 1.f/(1.f + expf(-pre));
                float rv = g_ring[rb+cc];
                (&o.x)[t] = g*rv + (1.f-g)*g_center[bb*N_+cc];
            }
            *(float4*)(g_fused + rb + c) = o;
        }
        __syncwarp();
    }
}

// ---------------- 8. LayerNorm over N (+ folded Wf bias and residual) ----------------
__global__ void ln_kernel(const float* __restrict__ gamma, const float* __restrict__ beta,
                          const float* __restrict__ bf, const float* __restrict__ x,
                          float* __restrict__ out) {
    int r = blockIdx.x, tid = threadIdx.x;   // 256 threads
    size_t base = (size_t)r*N_;
    float a  = g_h[base+tid]     + bf[tid]     + x[base+tid];
    float b2 = g_h[base+tid+256] + bf[tid+256] + x[base+tid+256];
    __shared__ float rs[256], rq[256];
    rs[tid] = a + b2;
    rq[tid] = a*a + b2*b2;
    __syncthreads();
    for (int o = 128; o > 0; o >>= 1) {
        if (tid < o) { rs[tid] += rs[tid+o]; rq[tid] += rq[tid+o]; }
        __syncthreads();
    }
    float mu  = rs[0] * (1.f/N_);
    float var = rq[0] * (1.f/N_) - mu*mu;
    float inv = rsqrtf(var + 1e-5f);
    out[base+tid]     = (a  - mu)*inv*gamma[tid]     + beta[tid];
    out[base+tid+256] = (b2 - mu)*inv*gamma[tid+256] + beta[tid+256];
}

// ---------------- launch ----------------
extern "C" void kernel_launch(void* const* d_in, const int* in_sizes, int n_in,
                              void* d_out, int out_size) {
    const float* x      = (const float*)d_in[0];
    const float* ve     = (const float*)d_in[1];
    const float* Wq     = (const float*)d_in[2];
    const float* bq     = (const float*)d_in[3];
    const float* Wk     = (const float*)d_in[4];
    const float* bk     = (const float*)d_in[5];
    const float* Wscore = (const float*)d_in[6];
    const float* bscore = (const float*)d_in[7];
    const float* Wc1    = (const float*)d_in[8];
    const float* bc1    = (const float*)d_in[9];
    const float* Wc2    = (const float*)d_in[10];
    const float* bc2    = (const float*)d_in[11];
    const float* Wcn    = (const float*)d_in[12];
    const float* bcn    = (const float*)d_in[13];
    const float* Wg     = (const float*)d_in[14];
    const float* bg     = (const float*)d_in[15];
    const float* Wf     = (const float*)d_in[16];
    const float* bf     = (const float*)d_in[17];
    const float* gamma  = (const float*)d_in[18];
    const float* beta   = (const float*)d_in[19];
    float* out = (float*)d_out;

    cudaFuncSetAttribute(gemm_wmma, cudaFuncAttributeMaxDynamicSharedMemorySize, GEMM_SMEM_);
    cudaFuncSetAttribute(ring_kernel, cudaFuncAttributeMaxDynamicSharedMemorySize, RING_SMEM_);

    qk_kernel<<<2, 256>>>(ve, Wq, bq, Wk, bk);                            // #0
    topk_kernel<<<512, 128>>>();                                          // #1
    score_kernel<<<dim3(8, B_), 256>>>(x, Wscore, bscore);                // #2
    ring_kernel<<<M_/RL, 512, RING_SMEM_>>>(x);                           // #3 <- profiled
    wsplit_kernel<<<N_*N_/256, 256>>>(Wg, 0);                             // #4 (Wg top half contiguous)
    wsplit_kernel<<<N_*N_/256, 256>>>(Wf, 1);                             // #5
    csum_kernel<<<dim3(4, B_), 128>>>(x);                                 // #6
    mlp_kernel<<<B_, 256>>>(Wc1, bc1, Wc2, bc2, Wcn, bcn);                // #7
    cg_kernel<<<dim3(B_, 4), 128>>>(Wg);                                  // #8
    gemm_wmma<<<dim3(M_/BM_, N_/BN_), 256, GEMM_SMEM_>>>(0, bg);          // #9
    gemm_wmma<<<dim3(M_/BM_, N_/BN_), 256, GEMM_SMEM_>>>(1, nullptr);     // #10
    ln_kernel<<<M_, 256>>>(gamma, beta, bf, x, out);                      // #11
}

// round 15
// speedup vs baseline: 1.4742x; 1.0625x over previous
#include <cuda_runtime.h>
#include <cuda_bf16.h>
#include <mma.h>
#include <math.h>
#include <stdint.h>

using namespace nvcuda;

#define B_ 32
#define L_ 720
#define N_ 512
#define H_ 16
#define D_ 64
#define TOPK_ 8
#define M_ (B_*L_)   // 23040

// ---------------- scratch (static device memory; no allocations) ----------------
__device__ float g_Q[N_*H_];
__device__ float g_K[N_*H_];
__device__ int   g_idx[N_*TOPK_];
__device__ float g_w[N_*TOPK_];
__device__ float g_logit[B_*L_];
__device__ float g_center_raw[B_*N_];
__device__ float g_center[B_*N_];
__device__ float g_cg[B_*N_];
__device__ float g_h[(size_t)M_*N_];
__device__ __align__(16) __nv_bfloat16 g_ringh[(size_t)M_*N_];
__device__ __align__(16) __nv_bfloat16 g_ringl[(size_t)M_*N_];
__device__ __align__(16) __nv_bfloat16 g_fusedh[(size_t)M_*N_];
__device__ __align__(16) __nv_bfloat16 g_fusedl[(size_t)M_*N_];
__device__ __align__(16) __nv_bfloat16 g_Wgh[N_*N_];
__device__ __align__(16) __nv_bfloat16 g_Wgl[N_*N_];
__device__ __align__(16) __nv_bfloat16 g_Wfh[N_*N_];
__device__ __align__(16) __nv_bfloat16 g_Wfl[N_*N_];

// ---------------- helpers ----------------
__device__ __forceinline__ void bsplit(float v, __nv_bfloat16& h, __nv_bfloat16& l) {
    h = __float2bfloat16(v);
    l = __float2bfloat16(v - __bfloat162float(h));
}
__device__ __forceinline__ uint32_t pack_split(float v) {
    __nv_bfloat16 h, l; bsplit(v, h, l);
    __nv_bfloat162 p(h, l);
    return *(uint32_t*)&p;
}

// ---------------- 0. elementwise W split ----------------
__global__ void wsplit_kernel(const float* __restrict__ W, int which) {
    int i = blockIdx.x * 256 + threadIdx.x;
    __nv_bfloat16* Th = which ? g_Wfh : g_Wgh;
    __nv_bfloat16* Tl = which ? g_Wfl : g_Wgl;
    __nv_bfloat16 h, l;
    bsplit(W[i], h, l);
    Th[i] = h; Tl[i] = l;
}

// ---------------- 1. Q/K projection ----------------
__global__ void qk_kernel(const float* __restrict__ ve,
                          const float* __restrict__ Wq, const float* __restrict__ bq,
                          const float* __restrict__ Wk, const float* __restrict__ bk) {
    int n = blockIdx.x * blockDim.x + threadIdx.x;
    if (n >= N_) return;
    float v[H_];
#pragma unroll
    for (int j = 0; j < H_; j++) v[j] = ve[n*H_+j];
#pragma unroll
    for (int h = 0; h < H_; h++) {
        float q = bq[h], k = bk[h];
#pragma unroll
        for (int j = 0; j < H_; j++) { q += v[j]*Wq[j*H_+h]; k += v[j]*Wk[j*H_+h]; }
        g_Q[n*H_+h] = q; g_K[n*H_+h] = k;
    }
}

// ---------------- 2. top-8 + softmax weights ----------------
__global__ void topk_kernel() {
    int n = blockIdx.x, tid = threadIdx.x;   // 128 threads
    __shared__ float sim[N_];
    __shared__ float q[H_];
    __shared__ float rv[128];
    __shared__ int   ri[128];
    __shared__ float tv[TOPK_];
    __shared__ int   tix[TOPK_];
    if (tid < H_) q[tid] = g_Q[n*H_+tid];
    __syncthreads();
    for (int m = tid; m < N_; m += 128) {
        float s = 0.f;
#pragma unroll
        for (int j = 0; j < H_; j++) s += q[j]*g_K[m*H_+j];
        sim[m] = (m == n) ? -1e9f : s;
    }
    __syncthreads();
    for (int t = 0; t < TOPK_; t++) {
        float bv = -1e30f; int bi = 0x7fffffff;
        for (int m = tid; m < N_; m += 128) {
            float s = sim[m];
            if (s > bv) { bv = s; bi = m; }
        }
        rv[tid] = bv; ri[tid] = bi;
        __syncthreads();
        for (int off = 64; off > 0; off >>= 1) {
            if (tid < off) {
                float ov = rv[tid+off]; int oi = ri[tid+off];
                if (ov > rv[tid] || (ov == rv[tid] && oi < ri[tid])) { rv[tid] = ov; ri[tid] = oi; }
            }
            __syncthreads();
        }
        if (tid == 0) { tv[t] = rv[0]; tix[t] = ri[0]; sim[ri[0]] = -1e30f; }
        __syncthreads();
    }
    if (tid == 0) {
        float mx = tv[0], e[TOPK_], s = 0.f;
#pragma unroll
        for (int t = 0; t < TOPK_; t++) { e[t] = expf(tv[t]-mx); s += e[t]; }
        float inv = 1.f/s;
#pragma unroll
        for (int t = 0; t < TOPK_; t++) { g_w[n*TOPK_+t] = e[t]*inv; g_idx[n*TOPK_+t] = tix[t]; }
    }
}

// ---------------- 3. score logits ----------------
__global__ void score_kernel(const float* __restrict__ x,
                             const float* __restrict__ Wscore,
                             const float* __restrict__ bscore) {
    int b = blockIdx.y, l0 = blockIdx.x * 90;
    int w = threadIdx.x >> 5, lane = threadIdx.x & 31;
    for (int l = l0 + w; l < l0 + 90; l += 8) {
        const float4* xr = (const float4*)(x + ((size_t)b*L_+l)*N_);
        const float4* wr = (const float4*)Wscore;
        float s = 0.f;
#pragma unroll
        for (int c = 0; c < 4; c++) {
            float4 v = xr[lane + c*32], ww = wr[lane + c*32];
            s += v.x*ww.x + v.y*ww.y + v.z*ww.z + v.w*ww.w;
        }
#pragma unroll
        for (int o = 16; o > 0; o >>= 1) s += __shfl_xor_sync(0xffffffffu, s, o);
        if (lane == 0) g_logit[b*L_+l] = s + bscore[0];
    }
}

// ---------------- 4. ring gather, conflict-free, 512 threads; hi/lo packed output -----
#define RL 32
#define RP 513
#define RING_SMEM_ ((2*RL*RP)*4 + N_*TOPK_*8)   // xt(f32) + ot(u32 packed) + pairs = 164 KB

__global__ __launch_bounds__(512) void ring_kernel(const float* __restrict__ x) {
    extern __shared__ float sm[];
    float*    xt = sm;                       // [RL][RP] fp32
    uint32_t* ot = (uint32_t*)(sm + RL*RP);  // [RL][RP] packed (hi, lo) bf16x2
    int2*     pr = (int2*)(sm + 2*RL*RP);    // [N_*TOPK_] packed (idx, w)
    const int tid = threadIdx.x;
    const size_t r0 = (size_t)blockIdx.x * RL;

    for (int e = tid; e < RL*N_; e += 512) {
        int i = e >> 9, c = e & 511;
        xt[i*RP + c] = x[(r0+i)*N_ + c];
    }
    for (int e = tid; e < N_*TOPK_; e += 512)
        pr[e] = make_int2(g_idx[e], __float_as_int(g_w[e]));
    __syncthreads();

    const int wid = tid >> 5, lane = tid & 31;   // 16 warps x 32 cols
    const float* xrow = xt + lane*RP;
#pragma unroll 4
    for (int n = wid*32; n < wid*32 + 32; n++) {
        float acc = 0.f;
#pragma unroll
        for (int k = 0; k < TOPK_; k++) {
            int2 p = pr[n*TOPK_ + k];
            acc += __int_as_float(p.y) * xrow[p.x];
        }
        ot[lane*RP + n] = pack_split(acc);
    }
    __syncthreads();

    for (int e = tid; e < RL*N_; e += 512) {
        int i = e >> 9, c = e & 511;
        uint32_t u = ot[i*RP + c];
        __nv_bfloat162 p = *(__nv_bfloat162*)&u;
        size_t go = (r0+i)*N_ + c;
        g_ringh[go] = p.x;
        g_ringl[go] = p.y;
    }
}

// ---------------- 5. fused softmax-over-L + weighted sum ----------------
__global__ void csum_kernel(const float* __restrict__ x) {
    int b = blockIdx.y, c = blockIdx.x*128 + threadIdx.x;
    int tid = threadIdx.x;   // 128 threads
    __shared__ float p[L_];
    __shared__ float red[128];
    for (int l = tid; l < L_; l += 128) p[l] = g_logit[b*L_+l];
    __syncthreads();
    float m = -1e30f;
    for (int l = tid; l < L_; l += 128) m = fmaxf(m, p[l]);
    red[tid] = m; __syncthreads();
    for (int o = 64; o > 0; o >>= 1) { if (tid < o) red[tid] = fmaxf(red[tid], red[tid+o]); __syncthreads(); }
    m = red[0]; __syncthreads();
    float s = 0.f;
    for (int l = tid; l < L_; l += 128) { float e = expf(p[l]-m); p[l] = e; s += e; }
    red[tid] = s; __syncthreads();
    for (int o = 64; o > 0; o >>= 1) { if (tid < o) red[tid] += red[tid+o]; __syncthreads(); }
    float inv = 1.f/red[0];
    __syncthreads();
    for (int l = tid; l < L_; l += 128) p[l] *= inv;
    __syncthreads();
    float acc = 0.f;
    const float* xb = x + (size_t)b*L_*N_ + c;
    for (int l = 0; l < L_; l++) acc += p[l]*xb[(size_t)l*N_];
    g_center_raw[b*N_+c] = acc;
}

// ---------------- 6a. center MLP ----------------
__global__ void mlp_kernel(const float* __restrict__ Wc1, const float* __restrict__ bc1,
                           const float* __restrict__ Wc2, const float* __restrict__ bc2,
                           const float* __restrict__ Wcn, const float* __restrict__ bcn) {
    int b = blockIdx.x, tid = threadIdx.x;   // 256 threads
    __shared__ float cr[N_];
    __shared__ float c1[D_];
    __shared__ float c2[D_];
    for (int n = tid; n < N_; n += 256) cr[n] = g_center_raw[b*N_+n];
    __syncthreads();
    {
        int d = tid >> 2, part = tid & 3;
        float s = 0.f;
        for (int n = part*128; n < part*128+128; n++) s += cr[n]*Wc1[n*D_+d];
        s += __shfl_xor_sync(0xffffffffu, s, 1);
        s += __shfl_xor_sync(0xffffffffu, s, 2);
        if (part == 0) {
            s += bc1[d];
            c1[d] = 0.5f*s*(1.f + erff(s*0.7071067811865475f));
        }
    }
    __syncthreads();
    if (tid < D_) {
        float s = bc2[tid];
#pragma unroll
        for (int e = 0; e < D_; e++) s += c1[e]*Wc2[e*D_+tid];
        c2[tid] = 0.5f*s*(1.f + erff(s*0.7071067811865475f));
    }
    __syncthreads();
    for (int n = tid; n < N_; n += 256) {
        float s = bcn[n];
#pragma unroll
        for (int d = 0; d < D_; d++) s += c2[d]*Wcn[d*N_+n];
        g_center[b*N_+n] = s;
    }
}

// ---------------- 6b. cg = center @ Wg[N:2N] ----------------
__global__ void cg_kernel(const float* __restrict__ Wg) {
    int b = blockIdx.x, n2 = blockIdx.y*128 + threadIdx.x;
    __shared__ float ctr[N_];
    for (int n = threadIdx.x; n < N_; n += 128) ctr[n] = g_center[b*N_+n];
    __syncthreads();
    float s = 0.f;
    for (int n = 0; n < N_; n++) s += ctr[n]*Wg[(size_t)(N_+n)*N_ + n2];
    g_cg[b*N_+n2] = s;
}

// ---------------- 7. WMMA bf16-split GEMM: ALL operands pre-split, staging = copies ---
#define BM_ 128
#define BN_ 128
#define BK_ 32
#define A_LD 40
#define W_LD 136
#define SA_H 0
#define SA_L 10240
#define SW_H 20480
#define SW_L 29184
#define GEMM_SMEM_ 37888
#define STG_LD 68

__global__ __launch_bounds__(256) void gemm_wmma(int mode,
                                                 const float* __restrict__ e0) {
    extern __shared__ __align__(128) char smem[];
    const int tid = threadIdx.x, wid = tid >> 5, lane = tid & 31;
    const int wm = wid >> 1, wn = wid & 1;
    const int row0 = blockIdx.x * BM_, col0 = blockIdx.y * BN_;

    const __nv_bfloat16* Ah = (mode == 0) ? g_ringh : g_fusedh;
    const __nv_bfloat16* Al = (mode == 0) ? g_ringl : g_fusedl;
    const __nv_bfloat16* Wh = (mode == 0) ? g_Wgh   : g_Wfh;
    const __nv_bfloat16* Wl = (mode == 0) ? g_Wgl   : g_Wfl;

    __nv_bfloat16* sAh = (__nv_bfloat16*)(smem + SA_H);
    __nv_bfloat16* sAl = (__nv_bfloat16*)(smem + SA_L);
    __nv_bfloat16* sWh = (__nv_bfloat16*)(smem + SW_H);
    __nv_bfloat16* sWl = (__nv_bfloat16*)(smem + SW_L);

    wmma::fragment<wmma::accumulator, 16, 16, 16, float> facc[2][4];
#pragma unroll
    for (int mi = 0; mi < 2; mi++)
#pragma unroll
        for (int p = 0; p < 4; p++) wmma::fill_fragment(facc[mi][p], 0.f);

    const int NKB = N_ / BK_;   // 16
    for (int kb = 0; kb < NKB; kb++) {
        const int k0 = kb * BK_;
        __syncthreads();
        // A tiles (hi+lo): 128 rows x 32 cols bf16 = 4 chunks/row -> 512 chunks/plane, 2/thread each
#pragma unroll
        for (int i = 0; i < 2; i++) {
            int c = i*256 + tid;
            int row = c >> 2, c8 = (c & 3) * 8;
            size_t go = (size_t)(row0+row)*N_ + k0 + c8;
            int o = row*A_LD + c8;
            *(uint4*)(sAh + o) = *(const uint4*)(Ah + go);
            *(uint4*)(sAl + o) = *(const uint4*)(Al + go);
        }
        // W tiles (hi+lo): 32 rows x 128 cols bf16 = 16 chunks/row -> 512 chunks/plane, 2/thread each
#pragma unroll
        for (int i = 0; i < 2; i++) {
            int c = i*256 + tid;
            int row = c >> 4, c8 = (c & 15) * 8;
            size_t go = (size_t)(k0+row)*N_ + col0 + c8;
            int o = row*W_LD + c8;
            *(uint4*)(sWh + o) = *(const uint4*)(Wh + go);
            *(uint4*)(sWl + o) = *(const uint4*)(Wl + go);
        }
        __syncthreads();

#pragma unroll
        for (int ks = 0; ks < 2; ks++) {
            wmma::fragment<wmma::matrix_a, 16, 16, 16, __nv_bfloat16, wmma::row_major> fah[2], fal[2];
#pragma unroll
            for (int mi = 0; mi < 2; mi++) {
                int aro = (wm*32 + mi*16) * A_LD + ks*16;
                wmma::load_matrix_sync(fah[mi], sAh + aro, A_LD);
                wmma::load_matrix_sync(fal[mi], sAl + aro, A_LD);
            }
#pragma unroll
            for (int p = 0; p < 4; p++) {
                wmma::fragment<wmma::matrix_b, 16, 16, 16, __nv_bfloat16, wmma::row_major> fbh, fbl;
                int bro = (ks*16) * W_LD + wn*64 + p*16;
                wmma::load_matrix_sync(fbh, sWh + bro, W_LD);
                wmma::load_matrix_sync(fbl, sWl + bro, W_LD);
#pragma unroll
                for (int mi = 0; mi < 2; mi++) {
                    wmma::mma_sync(facc[mi][p], fah[mi], fbh, facc[mi][p]);
                    wmma::mma_sync(facc[mi][p], fah[mi], fbl, facc[mi][p]);
                    wmma::mma_sync(facc[mi][p], fal[mi], fbh, facc[mi][p]);
                }
            }
        }
    }
    __syncthreads();

    if (mode == 1) {
#pragma unroll
        for (int mi = 0; mi < 2; mi++)
#pragma unroll
            for (int p = 0; p < 4; p++) {
                float* dst = g_h + (size_t)(row0 + wm*32 + mi*16)*N_ + col0 + wn*64 + p*16;
                wmma::store_matrix_sync(dst, facc[mi][p], N_, wmma::mem_row_major);
            }
        return;
    }

    // ---- mode 0 epilogue: gate mix; rv = ringh+ringl; output fused hi/lo ----
    float* wst = (float*)smem + wid * (16 * STG_LD);
#pragma unroll
    for (int mi = 0; mi < 2; mi++) {
#pragma unroll
        for (int p = 0; p < 4; p++)
            wmma::store_matrix_sync(wst + p*16, facc[mi][p], STG_LD, wmma::mem_row_major);
        __syncwarp();
        int r16 = lane >> 1;
        int coff = (lane & 1) * 32;
        int r = row0 + wm*32 + mi*16 + r16;
        int bb = r / L_;
        size_t rb = (size_t)r * N_;
        const float* myrow = wst + r16*STG_LD + coff;
#pragma unroll
        for (int q = 0; q < 8; q++) {
            float4 v = *(const float4*)(myrow + q*4);
            int c = col0 + wn*64 + coff + q*4;
            __nv_bfloat16 oh[4], ol[4];
#pragma unroll
            for (int t = 0; t < 4; t++) {
                int cc = c + t;
                float vv = (&v.x)[t];
                float pre = vv + g_cg[bb*N_+cc] + e0[cc];
                float g = 1.f/(1.f + expf(-pre));
                float rv = __bfloat162float(g_ringh[rb+cc]) + __bfloat162float(g_ringl[rb+cc]);
                float fu = g*rv + (1.f-g)*g_center[bb*N_+cc];
                bsplit(fu, oh[t], ol[t]);
            }
            *(__nv_bfloat162*)(g_fusedh + rb + c)     = __nv_bfloat162(oh[0], oh[1]);
            *(__nv_bfloat162*)(g_fusedh + rb + c + 2) = __nv_bfloat162(oh[2], oh[3]);
            *(__nv_bfloat162*)(g_fusedl + rb + c)     = __nv_bfloat162(ol[0], ol[1]);
            *(__nv_bfloat162*)(g_fusedl + rb + c + 2) = __nv_bfloat162(ol[2], ol[3]);
        }
        __syncwarp();
    }
}

// ---------------- 8. LayerNorm over N (+ folded Wf bias and residual) ----------------
__global__ void ln_kernel(const float* __restrict__ gamma, const float* __restrict__ beta,
                          const float* __restrict__ bf, const float* __restrict__ x,
                          float* __restrict__ out) {
    int r = blockIdx.x, tid = threadIdx.x;   // 256 threads
    size_t base = (size_t)r*N_;
    float a  = g_h[base+tid]     + bf[tid]     + x[base+tid];
    float b2 = g_h[base+tid+256] + bf[tid+256] + x[base+tid+256];
    __shared__ float rs[256], rq[256];
    rs[tid] = a + b2;
    rq[tid] = a*a + b2*b2;
    __syncthreads();
    for (int o = 128; o > 0; o >>= 1) {
        if (tid < o) { rs[tid] += rs[tid+o]; rq[tid] += rq[tid+o]; }
        __syncthreads();
    }
    float mu  = rs[0] * (1.f/N_);
    float var = rq[0] * (1.f/N_) - mu*mu;
    float inv = rsqrtf(var + 1e-5f);
    out[base+tid]     = (a  - mu)*inv*gamma[tid]     + beta[tid];
    out[base+tid+256] = (b2 - mu)*inv*gamma[tid+256] + beta[tid+256];
}

// ---------------- launch ----------------
extern "C" void kernel_launch(void* const* d_in, const int* in_sizes, int n_in,
                              void* d_out, int out_size) {
    const float* x      = (const float*)d_in[0];
    const float* ve     = (const float*)d_in[1];
    const float* Wq     = (const float*)d_in[2];
    const float* bq     = (const float*)d_in[3];
    const float* Wk     = (const float*)d_in[4];
    const float* bk     = (const float*)d_in[5];
    const float* Wscore = (const float*)d_in[6];
    const float* bscore = (const float*)d_in[7];
    const float* Wc1    = (const float*)d_in[8];
    const float* bc1    = (const float*)d_in[9];
    const float* Wc2    = (const float*)d_in[10];
    const float* bc2    = (const float*)d_in[11];
    const float* Wcn    = (const float*)d_in[12];
    const float* bcn    = (const float*)d_in[13];
    const float* Wg     = (const float*)d_in[14];
    const float* bg     = (const float*)d_in[15];
    const float* Wf     = (const float*)d_in[16];
    const float* bf     = (const float*)d_in[17];
    const float* gamma  = (const float*)d_in[18];
    const float* beta   = (const float*)d_in[19];
    float* out = (float*)d_out;

    cudaFuncSetAttribute(gemm_wmma, cudaFuncAttributeMaxDynamicSharedMemorySize, GEMM_SMEM_);
    cudaFuncSetAttribute(ring_kernel, cudaFuncAttributeMaxDynamicSharedMemorySize, RING_SMEM_);

    qk_kernel<<<2, 256>>>(ve, Wq, bq, Wk, bk);                            // #0
    topk_kernel<<<512, 128>>>();                                          // #1
    score_kernel<<<dim3(8, B_), 256>>>(x, Wscore, bscore);                // #2
    ring_kernel<<<M_/RL, 512, RING_SMEM_>>>(x);                           // #3 <- profiled
    wsplit_kernel<<<N_*N_/256, 256>>>(Wg, 0);                             // #4
    wsplit_kernel<<<N_*N_/256, 256>>>(Wf, 1);                             // #5
    csum_kernel<<<dim3(4, B_), 128>>>(x);                                 // #6
    mlp_kernel<<<B_, 256>>>(Wc1, bc1, Wc2, bc2, Wcn, bcn);                // #7
    cg_kernel<<<dim3(B_, 4), 128>>>(Wg);                                  // #8
    gemm_wmma<<<dim3(M_/BM_, N_/BN_), 256, GEMM_SMEM_>>>(0, bg);          // #9
    gemm_wmma<<<dim3(M_/BM_, N_/BN_), 256, GEMM_SMEM_>>>(1, nullptr);     // #10
    ln_kernel<<<M_, 256>>>(gamma, beta, bf, x, out);                      // #11
}